// round 7
// baseline (speedup 1.0000x reference)
#include <cuda_runtime.h>
#include <cuda_fp16.h>
#include <cstdint>

#define BB 4
#define CC 64
#define NNPOS 4096
#define HH 64
#define WW 64

// Scratch (__device__ globals; no allocs allowed)
__device__ __half g_xn[BB * CC * NNPOS];           // LN output (B,C,N) fp16
__device__ __half g_q[BB * NNPOS * CC];            // Q fp16 (B,N,C), x (0.125*log2e) folded
__device__ __half g_k[BB * NNPOS * CC];            // K fp16 (B,N,C)
__device__ __half g_v[BB * CC * NNPOS];            // V fp16 (B,C,N)
__device__ float g_o[BB * NNPOS * CC];             // attn out (B,N,C) fp32

#define QSCALE 0.18033688011112293f   // 0.125 * log2(e)
#define ONES2 0x3C003C00u              // half2(1.0, 1.0)

// ---------------- helpers ----------------
__device__ __forceinline__ uint32_t h2u(__half2 h) { return *reinterpret_cast<uint32_t*>(&h); }

__device__ __forceinline__ void ldsm4(uint32_t* r, uint32_t addr) {
    asm volatile("ldmatrix.sync.aligned.m8n8.x4.shared.b16 {%0,%1,%2,%3}, [%4];"
                 : "=r"(r[0]), "=r"(r[1]), "=r"(r[2]), "=r"(r[3]) : "r"(addr));
}
__device__ __forceinline__ void mma16816(float* d, const uint32_t* a, uint32_t b0, uint32_t b1) {
    asm volatile("mma.sync.aligned.m16n8k16.row.col.f32.f16.f16.f32 "
                 "{%0,%1,%2,%3},{%4,%5,%6,%7},{%8,%9},{%0,%1,%2,%3};"
                 : "+f"(d[0]), "+f"(d[1]), "+f"(d[2]), "+f"(d[3])
                 : "r"(a[0]), "r"(a[1]), "r"(a[2]), "r"(a[3]), "r"(b0), "r"(b1));
}
__device__ __forceinline__ void cpasync16(uint32_t dst, const void* src) {
    asm volatile("cp.async.cg.shared.global [%0], [%1], 16;" :: "r"(dst), "l"(src));
}
__device__ __forceinline__ void cpcommit() { asm volatile("cp.async.commit_group;"); }
__device__ __forceinline__ void cpwait0()  { asm volatile("cp.async.wait_group 0;"); }
__device__ __forceinline__ void cpwait1()  { asm volatile("cp.async.wait_group 1;"); }

// p_f16x2 = 2^{slo, shi} via one cvt + one MUFU ex2 (pairwise)
__device__ __forceinline__ uint32_t exp2_f16x2(float slo, float shi) {
    uint32_t h, r;
    asm("cvt.rn.f16x2.f32 %0, %1, %2;" : "=r"(h) : "f"(shi), "f"(slo));
    asm("ex2.approx.f16x2 %0, %1;" : "=r"(r) : "r"(h));
    return r;
}

// ---------------------------------------------------------------------------
// 1) LayerNorm over channels -> g_xn (B,C,N) fp16
// ---------------------------------------------------------------------------
__global__ void ln_kernel(const float* __restrict__ x,
                          const float* __restrict__ g,
                          const float* __restrict__ be) {
    int idx = blockIdx.x * blockDim.x + threadIdx.x;
    int b = idx >> 12;
    int i = idx & 4095;
    const float* xp = x + (size_t)b * CC * NNPOS + i;
    float vals[CC];
    float s = 0.f;
#pragma unroll
    for (int c = 0; c < CC; c++) { vals[c] = xp[(size_t)c * NNPOS]; s += vals[c]; }
    float mu = s * (1.f / 64.f);
    float vs = 0.f;
#pragma unroll
    for (int c = 0; c < CC; c++) { float d = vals[c] - mu; vs += d * d; }
    float rstd = rsqrtf(vs * (1.f / 64.f) + 1e-5f);
    __half* op = g_xn + (size_t)b * CC * NNPOS + i;
#pragma unroll
    for (int c = 0; c < CC; c++)
        op[(size_t)c * NNPOS] = __float2half_rn((vals[c] - mu) * rstd * __ldg(&g[c]) + __ldg(&be[c]));
}

// ---------------------------------------------------------------------------
// 2) q = (wq @ xn + bq) * QSCALE -> fp16 (B,N,C)
// ---------------------------------------------------------------------------
__global__ __launch_bounds__(256) void qproj_kernel(const float* __restrict__ wq,
                                                    const float* __restrict__ bq) {
    __shared__ float Xs[CC * 64];
    __shared__ float Wsm[CC * CC];
    int b = blockIdx.y;
    int i0 = blockIdx.x * 64;
    int tid = threadIdx.x;
    for (int t = tid; t < CC * CC / 4; t += 256)
        ((float4*)Wsm)[t] = ((const float4*)wq)[t];
    const __half* xp = g_xn + (size_t)b * CC * NNPOS + i0;
    for (int t = tid; t < CC * 16; t += 256) {
        int c = t >> 4, f = t & 15;
        uint2 raw = *(const uint2*)&xp[(size_t)c * NNPOS + f * 4];
        __half2 ha = *(__half2*)&raw.x, hb = *(__half2*)&raw.y;
        float2 fa = __half22float2(ha), fb = __half22float2(hb);
        *(float4*)&Xs[c * 64 + f * 4] = make_float4(fa.x, fa.y, fb.x, fb.y);
    }
    __syncthreads();
    int to = tid >> 4, tx = tid & 15;
    float acc[4][4] = {};
#pragma unroll 8
    for (int c = 0; c < CC; c++) {
        float4 xv = *(float4*)&Xs[c * 64 + tx * 4];
        float w0 = Wsm[(to * 4 + 0) * 64 + c];
        float w1 = Wsm[(to * 4 + 1) * 64 + c];
        float w2 = Wsm[(to * 4 + 2) * 64 + c];
        float w3 = Wsm[(to * 4 + 3) * 64 + c];
        acc[0][0] += w0 * xv.x; acc[0][1] += w0 * xv.y; acc[0][2] += w0 * xv.z; acc[0][3] += w0 * xv.w;
        acc[1][0] += w1 * xv.x; acc[1][1] += w1 * xv.y; acc[1][2] += w1 * xv.z; acc[1][3] += w1 * xv.w;
        acc[2][0] += w2 * xv.x; acc[2][1] += w2 * xv.y; acc[2][2] += w2 * xv.z; acc[2][3] += w2 * xv.w;
        acc[3][0] += w3 * xv.x; acc[3][1] += w3 * xv.y; acc[3][2] += w3 * xv.z; acc[3][3] += w3 * xv.w;
    }
    float bb[4];
#pragma unroll
    for (int r = 0; r < 4; r++) bb[r] = __ldg(&bq[to * 4 + r]);
#pragma unroll
    for (int s = 0; s < 4; s++) {
        int i = i0 + tx * 4 + s;
        float v0 = (acc[0][s] + bb[0]) * QSCALE;
        float v1 = (acc[1][s] + bb[1]) * QSCALE;
        float v2 = (acc[2][s] + bb[2]) * QSCALE;
        float v3 = (acc[3][s] + bb[3]) * QSCALE;
        size_t base = (size_t)(b * NNPOS + i) * CC + to * 4;
        *(uint2*)&g_q[base] = make_uint2(h2u(__floats2half2_rn(v0, v1)),
                                         h2u(__floats2half2_rn(v2, v3)));
    }
}

// ---------------------------------------------------------------------------
// 3) Depthwise 3x3: k -> fp16 (B,N,C), v -> fp16 (B,C,N)
// ---------------------------------------------------------------------------
__global__ __launch_bounds__(128) void dwconv_kernel(const float* __restrict__ wk,
                                                     const float* __restrict__ bk,
                                                     const float* __restrict__ wv,
                                                     const float* __restrict__ bv) {
    int t = threadIdx.x;
    int pos = blockIdx.x * 128 + t;
    int cg = blockIdx.y * 16;
    int b = blockIdx.z;
    int h = pos >> 6, w = pos & 63;
    uint32_t khp[8];
    uint32_t khprev = 0;
#pragma unroll
    for (int ci = 0; ci < 16; ci++) {
        int c = cg + ci;
        const __half* xp = g_xn + (size_t)(b * CC + c) * NNPOS;
        const float* wkp = wk + c * 9;
        const float* wvp = wv + c * 9;
        float sk = __ldg(&bk[c]);
        float sv = __ldg(&bv[c]);
#pragma unroll
        for (int dh = 0; dh < 3; dh++) {
            int hh = h + dh - 1;
            if (hh < 0 || hh >= HH) continue;
#pragma unroll
            for (int dw = 0; dw < 3; dw++) {
                int ww = w + dw - 1;
                if (ww < 0 || ww >= WW) continue;
                float xv = __half2float(xp[hh * WW + ww]);
                sk += xv * __ldg(&wkp[dh * 3 + dw]);
                sv += xv * __ldg(&wvp[dh * 3 + dw]);
            }
        }
        g_v[(size_t)(b * CC + c) * NNPOS + pos] = __float2half_rn(sv);
        uint32_t hb = (uint32_t)__half_as_ushort(__float2half_rn(sk));
        if (ci & 1) khp[ci >> 1] = khprev | (hb << 16);
        else khprev = hb;
    }
    size_t kbase = (size_t)(b * NNPOS + pos) * CC + cg;
    *(uint4*)&g_k[kbase]     = make_uint4(khp[0], khp[1], khp[2], khp[3]);
    *(uint4*)&g_k[kbase + 8] = make_uint4(khp[4], khp[5], khp[6], khp[7]);
}

// ---------------------------------------------------------------------------
// 4) HMMA flash attention, software-pipelined: S(t+1) interleaved with PV(t).
//    grid (32, B) = 128 blocks, 256 threads = 8 warps x 16 query rows.
//    3 cp.async buffers; softmax via ex2.approx.f16x2; l via ones-MMA.
// ---------------------------------------------------------------------------
#define KROWB 144
#define VROWB 272
#define KBYTES (128 * KROWB)        // 18432
#define VBYTES (64 * VROWB)         // 17408
#define BUFB (KBYTES + VBYTES)      // 35840
#define ATTN_SMEM (3 * BUFB)        // 107520

__device__ __forceinline__ void prefetch_tile(char* smp, int s, int b, int jt, int tid) {
    // K: 128 rows x 128B. thread -> row j = tid>>1, half hf = tid&1 (64B)
    {
        int j = tid >> 1, hf = tid & 1;
        const __half* src = g_k + (size_t)(b * NNPOS + jt + j) * CC + hf * 32;
        uint32_t dst = (uint32_t)__cvta_generic_to_shared(smp + s * BUFB + j * KROWB + hf * 64);
#pragma unroll
        for (int u = 0; u < 4; u++) cpasync16(dst + u * 16, src + u * 8);
    }
    // V: 64 rows x 256B. thread -> row c = tid>>2, quarter q = tid&3 (64B)
    {
        int c = tid >> 2, q = tid & 3;
        const __half* src = g_v + (size_t)(b * CC + c) * NNPOS + jt + q * 32;
        uint32_t dst = (uint32_t)__cvta_generic_to_shared(smp + s * BUFB + KBYTES + c * VROWB + q * 64);
#pragma unroll
        for (int u = 0; u < 4; u++) cpasync16(dst + u * 16, src + u * 8);
    }
}

__global__ __launch_bounds__(256, 1) void attn_kernel() {
    extern __shared__ char smp[];
    int tid = threadIdx.x;
    int w = tid >> 5, lane = tid & 31;
    int b = blockIdx.y;
    int i0 = blockIdx.x * 128;
    int g = lane >> 2, t4 = lane & 3;

    // B-type ldmatrix.x4 lane offset pieces
    int laneRowB = (lane & 7) + ((lane & 16) >> 1);
    int laneKB   = (lane & 8) << 1;
    uint32_t loffK = (uint32_t)(laneRowB * KROWB + laneKB);
    uint32_t loffV = (uint32_t)(laneRowB * VROWB + laneKB);
    uint32_t smbase = (uint32_t)__cvta_generic_to_shared(smp);

    prefetch_tile(smp, 0, b, 0, tid);
    cpcommit();
    prefetch_tile(smp, 1, b, 128, tid);
    cpcommit();

    // Q A-fragments resident: qA[ks][0..3], ks = 0..3 (K=64)
    uint32_t qA[4][4];
    {
        size_t row0 = (size_t)(b * NNPOS + i0 + w * 16 + g) * CC;
        size_t row8 = row0 + 8 * CC;
#pragma unroll
        for (int ks = 0; ks < 4; ks++) {
            int col = 2 * t4 + 16 * ks;
            qA[ks][0] = *(const uint32_t*)(g_q + row0 + col);
            qA[ks][1] = *(const uint32_t*)(g_q + row8 + col);
            qA[ks][2] = *(const uint32_t*)(g_q + row0 + col + 8);
            qA[ks][3] = *(const uint32_t*)(g_q + row8 + col + 8);
        }
    }

    float oacc[8][4] = {};
    float lacc[4] = {};
    float sacc[16][4];

    // ---- S(0) standalone (buf 0) ----
    cpwait1();
    __syncthreads();
#pragma unroll
    for (int i = 0; i < 16; i++)
#pragma unroll
        for (int j = 0; j < 4; j++) sacc[i][j] = 0.f;
    {
        uint32_t kb = smbase + loffK;
        uint32_t b4[2][4];
        ldsm4(b4[0], kb);
#pragma unroll
        for (int it = 0; it < 32; it++) {
            int ks = it >> 3, np = it & 7;
            int cur = it & 1;
            if (it < 31) {
                int nx = it + 1;
                ldsm4(b4[cur ^ 1], kb + (uint32_t)((nx & 7) * (16 * KROWB) + (nx >> 3) * 32));
            }
            mma16816(sacc[2 * np],     qA[ks], b4[cur][0], b4[cur][1]);
            mma16816(sacc[2 * np + 1], qA[ks], b4[cur][2], b4[cur][3]);
        }
    }

    for (int t = 0; t < 32; t++) {
        // pA(t) from sacc; sacc is then free for S(t+1)
        uint32_t pA[8][4];
#pragma unroll
        for (int c = 0; c < 8; c++) {
            float* se = sacc[2 * c];
            float* so = sacc[2 * c + 1];
            pA[c][0] = exp2_f16x2(se[0], se[1]);
            pA[c][1] = exp2_f16x2(se[2], se[3]);
            pA[c][2] = exp2_f16x2(so[0], so[1]);
            pA[c][3] = exp2_f16x2(so[2], so[3]);
        }

        // barrier: all warps finished PV(t-1) reads of buf[(t+2)%3] before overwrite
        __syncthreads();
        if (t + 2 < 32) { prefetch_tile(smp, (t + 2) % 3, b, (t + 2) * 128, tid); cpcommit(); }
        if (t + 2 < 32) cpwait1(); else cpwait0();   // buf[(t+1)%3] ready
        __syncthreads();

        uint32_t kbN = smbase + (uint32_t)(((t + 1) % 3) * BUFB) + loffK;   // K(t+1)
        uint32_t vbC = smbase + (uint32_t)((t % 3) * BUFB + KBYTES) + loffV; // V(t)
        bool doS = (t < 31);

        if (doS) {
#pragma unroll
            for (int i = 0; i < 16; i++)
#pragma unroll
                for (int j = 0; j < 4; j++) sacc[i][j] = 0.f;
        }

        // ---- interleaved: S(t+1) [32 steps] + PV(t) [8 chunks x (lacc + 4 steps)] ----
#pragma unroll
        for (int c = 0; c < 8; c++) {
            mma16816(lacc, pA[c], ONES2, ONES2);
#pragma unroll
            for (int j = 0; j < 4; j++) {
                int it = c * 4 + j;
                if (doS) {
                    uint32_t b4[4];
                    ldsm4(b4, kbN + (uint32_t)((it & 7) * (16 * KROWB) + (it >> 3) * 32));
                    int np = it & 7, ks = it >> 3;
                    mma16816(sacc[2 * np],     qA[ks], b4[0], b4[1]);
                    mma16816(sacc[2 * np + 1], qA[ks], b4[2], b4[3]);
                }
                uint32_t v4[4];
                ldsm4(v4, vbC + (uint32_t)(j * (16 * VROWB) + c * 32));
                mma16816(oacc[2 * j],     pA[c], v4[0], v4[1]);
                mma16816(oacc[2 * j + 1], pA[c], v4[2], v4[3]);
            }
        }
    }

    // lacc[0] = rowsum(row g), lacc[2] = rowsum(row g+8)
    float inv0 = 1.f / lacc[0], inv1 = 1.f / lacc[2];

    float* orow0 = g_o + (size_t)(b * NNPOS + i0 + w * 16 + g) * CC;
    float* orow8 = orow0 + 8 * CC;
#pragma unroll
    for (int nt = 0; nt < 8; nt++) {
        int c = nt * 8 + 2 * t4;
        *(float2*)&orow0[c] = make_float2(oacc[nt][0] * inv0, oacc[nt][1] * inv0);
        *(float2*)&orow8[c] = make_float2(oacc[nt][2] * inv1, oacc[nt][3] * inv1);
    }
}

// ---------------------------------------------------------------------------
// 5) out = wo @ O + bo + x   (O in (B,N,C))
// ---------------------------------------------------------------------------
#define XS_LD 68
__global__ __launch_bounds__(256) void oproj_kernel(const float* __restrict__ wo,
                                                    const float* __restrict__ bo,
                                                    const float* __restrict__ x,
                                                    float* __restrict__ out) {
    __shared__ float Xs[64 * XS_LD];
    __shared__ float Wsm[CC * CC];
    int b = blockIdx.y;
    int i0 = blockIdx.x * 64;
    int tid = threadIdx.x;
    for (int t = tid; t < CC * CC / 4; t += 256)
        ((float4*)Wsm)[t] = ((const float4*)wo)[t];
    {
        int i = tid >> 2, q4 = tid & 3;
        const float* orow = g_o + (size_t)(b * NNPOS + i0 + i) * CC;
#pragma unroll
        for (int u = 0; u < 4; u++) {
            int c = q4 * 16 + u * 4;
            *(float4*)&Xs[i * XS_LD + c] = *(const float4*)&orow[c];
        }
    }
    __syncthreads();
    int to = tid >> 4, tx = tid & 15;
    float acc[4][4] = {};
#pragma unroll 4
    for (int c4 = 0; c4 < CC; c4 += 4) {
        float4 wv[4], xv[4];
#pragma unroll
        for (int r = 0; r < 4; r++) wv[r] = *(float4*)&Wsm[(to * 4 + r) * 64 + c4];
#pragma unroll
        for (int s = 0; s < 4; s++) xv[s] = *(float4*)&Xs[(tx * 4 + s) * XS_LD + c4];
#pragma unroll
        for (int r = 0; r < 4; r++)
#pragma unroll
            for (int s = 0; s < 4; s++)
                acc[r][s] += wv[r].x * xv[s].x + wv[r].y * xv[s].y +
                             wv[r].z * xv[s].z + wv[r].w * xv[s].w;
    }
#pragma unroll
    for (int r = 0; r < 4; r++) {
        int o = to * 4 + r;
        float bias = __ldg(&bo[o]);
        size_t base = (size_t)(b * CC + o) * NNPOS + i0 + tx * 4;
        float4 xr = *(const float4*)&x[base];
        float4 res = make_float4(acc[r][0] + bias + xr.x, acc[r][1] + bias + xr.y,
                                 acc[r][2] + bias + xr.z, acc[r][3] + bias + xr.w);
        *(float4*)&out[base] = res;
    }
}

// ---------------------------------------------------------------------------
extern "C" void kernel_launch(void* const* d_in, const int* in_sizes, int n_in,
                              void* d_out, int out_size) {
    (void)in_sizes; (void)n_in; (void)out_size;
    const float* x    = (const float*)d_in[0];
    const float* ln_g = (const float*)d_in[1];
    const float* ln_b = (const float*)d_in[2];
    const float* wq   = (const float*)d_in[3];
    const float* bq   = (const float*)d_in[4];
    const float* wk   = (const float*)d_in[5];
    const float* bk   = (const float*)d_in[6];
    const float* wv   = (const float*)d_in[7];
    const float* bv   = (const float*)d_in[8];
    const float* wo   = (const float*)d_in[9];
    const float* bo   = (const float*)d_in[10];
    float* out = (float*)d_out;

    ln_kernel<<<(BB * NNPOS) / 256, 256>>>(x, ln_g, ln_b);
    qproj_kernel<<<dim3(NNPOS / 64, BB), 256>>>(wq, bq);
    dwconv_kernel<<<dim3(NNPOS / 128, 4, BB), 128>>>(wk, bk, wv, bv);
    cudaFuncSetAttribute(attn_kernel, cudaFuncAttributeMaxDynamicSharedMemorySize, ATTN_SMEM);
    attn_kernel<<<dim3(NNPOS / 128, BB), 256, ATTN_SMEM>>>();
    oproj_kernel<<<dim3(NNPOS / 64, BB), 256>>>(wo, bo, x, out);
}

// round 8
// speedup vs baseline: 1.2022x; 1.2022x over previous
#include <cuda_runtime.h>
#include <cuda_fp16.h>
#include <cstdint>

#define BB 4
#define CC 64
#define NNPOS 4096
#define HH 64
#define WW 64

// Scratch (__device__ globals; no allocs allowed)
__device__ __half g_xn[BB * CC * NNPOS];           // LN output (B,C,N) fp16
__device__ __half g_q[BB * NNPOS * CC];            // Q fp16 (B,N,C), x (0.125*log2e) folded
__device__ __half g_k[BB * NNPOS * CC];            // K fp16 (B,N,C)
__device__ __half g_v[BB * CC * NNPOS];            // V fp16 (B,C,N)

#define QSCALE 0.18033688011112293f   // 0.125 * log2(e)
#define ONES2 0x3C003C00u              // half2(1.0, 1.0)

// ---------------- helpers ----------------
__device__ __forceinline__ uint32_t h2u(__half2 h) { return *reinterpret_cast<uint32_t*>(&h); }

__device__ __forceinline__ void ldsm4(uint32_t* r, uint32_t addr) {
    asm volatile("ldmatrix.sync.aligned.m8n8.x4.shared.b16 {%0,%1,%2,%3}, [%4];"
                 : "=r"(r[0]), "=r"(r[1]), "=r"(r[2]), "=r"(r[3]) : "r"(addr));
}
__device__ __forceinline__ void mma16816(float* d, const uint32_t* a, uint32_t b0, uint32_t b1) {
    asm volatile("mma.sync.aligned.m16n8k16.row.col.f32.f16.f16.f32 "
                 "{%0,%1,%2,%3},{%4,%5,%6,%7},{%8,%9},{%0,%1,%2,%3};"
                 : "+f"(d[0]), "+f"(d[1]), "+f"(d[2]), "+f"(d[3])
                 : "r"(a[0]), "r"(a[1]), "r"(a[2]), "r"(a[3]), "r"(b0), "r"(b1));
}
__device__ __forceinline__ void cpasync16(uint32_t dst, const void* src) {
    asm volatile("cp.async.cg.shared.global [%0], [%1], 16;" :: "r"(dst), "l"(src));
}
__device__ __forceinline__ void cpcommit() { asm volatile("cp.async.commit_group;"); }
__device__ __forceinline__ void cpwait0()  { asm volatile("cp.async.wait_group 0;"); }

// p_f16x2 = 2^{slo, shi} via one cvt + one MUFU ex2 (pairwise)
__device__ __forceinline__ uint32_t exp2_f16x2(float slo, float shi) {
    uint32_t h, r;
    asm("cvt.rn.f16x2.f32 %0, %1, %2;" : "=r"(h) : "f"(shi), "f"(slo));
    asm("ex2.approx.f16x2 %0, %1;" : "=r"(r) : "r"(h));
    return r;
}

// ---------------------------------------------------------------------------
// 1) LayerNorm over channels -> g_xn (B,C,N) fp16
// ---------------------------------------------------------------------------
__global__ void ln_kernel(const float* __restrict__ x,
                          const float* __restrict__ g,
                          const float* __restrict__ be) {
    int idx = blockIdx.x * blockDim.x + threadIdx.x;
    int b = idx >> 12;
    int i = idx & 4095;
    const float* xp = x + (size_t)b * CC * NNPOS + i;
    float vals[CC];
    float s = 0.f;
#pragma unroll
    for (int c = 0; c < CC; c++) { vals[c] = xp[(size_t)c * NNPOS]; s += vals[c]; }
    float mu = s * (1.f / 64.f);
    float vs = 0.f;
#pragma unroll
    for (int c = 0; c < CC; c++) { float d = vals[c] - mu; vs += d * d; }
    float rstd = rsqrtf(vs * (1.f / 64.f) + 1e-5f);
    __half* op = g_xn + (size_t)b * CC * NNPOS + i;
#pragma unroll
    for (int c = 0; c < CC; c++)
        op[(size_t)c * NNPOS] = __float2half_rn((vals[c] - mu) * rstd * __ldg(&g[c]) + __ldg(&be[c]));
}

// ---------------------------------------------------------------------------
// 2) q = (wq @ xn + bq) * QSCALE -> fp16 (B,N,C)
// ---------------------------------------------------------------------------
__global__ __launch_bounds__(256) void qproj_kernel(const float* __restrict__ wq,
                                                    const float* __restrict__ bq) {
    __shared__ float Xs[CC * 64];
    __shared__ float Wsm[CC * CC];
    int b = blockIdx.y;
    int i0 = blockIdx.x * 64;
    int tid = threadIdx.x;
    for (int t = tid; t < CC * CC / 4; t += 256)
        ((float4*)Wsm)[t] = ((const float4*)wq)[t];
    const __half* xp = g_xn + (size_t)b * CC * NNPOS + i0;
    for (int t = tid; t < CC * 16; t += 256) {
        int c = t >> 4, f = t & 15;
        uint2 raw = *(const uint2*)&xp[(size_t)c * NNPOS + f * 4];
        __half2 ha = *(__half2*)&raw.x, hb = *(__half2*)&raw.y;
        float2 fa = __half22float2(ha), fb = __half22float2(hb);
        *(float4*)&Xs[c * 64 + f * 4] = make_float4(fa.x, fa.y, fb.x, fb.y);
    }
    __syncthreads();
    int to = tid >> 4, tx = tid & 15;
    float acc[4][4] = {};
#pragma unroll 8
    for (int c = 0; c < CC; c++) {
        float4 xv = *(float4*)&Xs[c * 64 + tx * 4];
        float w0 = Wsm[(to * 4 + 0) * 64 + c];
        float w1 = Wsm[(to * 4 + 1) * 64 + c];
        float w2 = Wsm[(to * 4 + 2) * 64 + c];
        float w3 = Wsm[(to * 4 + 3) * 64 + c];
        acc[0][0] += w0 * xv.x; acc[0][1] += w0 * xv.y; acc[0][2] += w0 * xv.z; acc[0][3] += w0 * xv.w;
        acc[1][0] += w1 * xv.x; acc[1][1] += w1 * xv.y; acc[1][2] += w1 * xv.z; acc[1][3] += w1 * xv.w;
        acc[2][0] += w2 * xv.x; acc[2][1] += w2 * xv.y; acc[2][2] += w2 * xv.z; acc[2][3] += w2 * xv.w;
        acc[3][0] += w3 * xv.x; acc[3][1] += w3 * xv.y; acc[3][2] += w3 * xv.z; acc[3][3] += w3 * xv.w;
    }
    float bb[4];
#pragma unroll
    for (int r = 0; r < 4; r++) bb[r] = __ldg(&bq[to * 4 + r]);
#pragma unroll
    for (int s = 0; s < 4; s++) {
        int i = i0 + tx * 4 + s;
        float v0 = (acc[0][s] + bb[0]) * QSCALE;
        float v1 = (acc[1][s] + bb[1]) * QSCALE;
        float v2 = (acc[2][s] + bb[2]) * QSCALE;
        float v3 = (acc[3][s] + bb[3]) * QSCALE;
        size_t base = (size_t)(b * NNPOS + i) * CC + to * 4;
        *(uint2*)&g_q[base] = make_uint2(h2u(__floats2half2_rn(v0, v1)),
                                         h2u(__floats2half2_rn(v2, v3)));
    }
}

// ---------------------------------------------------------------------------
// 3) Depthwise 3x3: k -> fp16 (B,N,C), v -> fp16 (B,C,N)
// ---------------------------------------------------------------------------
__global__ __launch_bounds__(128) void dwconv_kernel(const float* __restrict__ wk,
                                                     const float* __restrict__ bk,
                                                     const float* __restrict__ wv,
                                                     const float* __restrict__ bv) {
    int t = threadIdx.x;
    int pos = blockIdx.x * 128 + t;
    int cg = blockIdx.y * 16;
    int b = blockIdx.z;
    int h = pos >> 6, w = pos & 63;
    uint32_t khp[8];
    uint32_t khprev = 0;
#pragma unroll
    for (int ci = 0; ci < 16; ci++) {
        int c = cg + ci;
        const __half* xp = g_xn + (size_t)(b * CC + c) * NNPOS;
        const float* wkp = wk + c * 9;
        const float* wvp = wv + c * 9;
        float sk = __ldg(&bk[c]);
        float sv = __ldg(&bv[c]);
#pragma unroll
        for (int dh = 0; dh < 3; dh++) {
            int hh = h + dh - 1;
            if (hh < 0 || hh >= HH) continue;
#pragma unroll
            for (int dw = 0; dw < 3; dw++) {
                int ww = w + dw - 1;
                if (ww < 0 || ww >= WW) continue;
                float xv = __half2float(xp[hh * WW + ww]);
                sk += xv * __ldg(&wkp[dh * 3 + dw]);
                sv += xv * __ldg(&wvp[dh * 3 + dw]);
            }
        }
        g_v[(size_t)(b * CC + c) * NNPOS + pos] = __float2half_rn(sv);
        uint32_t hb = (uint32_t)__half_as_ushort(__float2half_rn(sk));
        if (ci & 1) khp[ci >> 1] = khprev | (hb << 16);
        else khprev = hb;
    }
    size_t kbase = (size_t)(b * NNPOS + pos) * CC + cg;
    *(uint4*)&g_k[kbase]     = make_uint4(khp[0], khp[1], khp[2], khp[3]);
    *(uint4*)&g_k[kbase + 8] = make_uint4(khp[4], khp[5], khp[6], khp[7]);
}

// ---------------------------------------------------------------------------
// 4) HMMA flash attention + fused out-projection + bias + residual.
//    grid (32, B) = 128 blocks, 256 threads = 8 warps x 16 query rows.
//    Main loop = R6 (double-buffered cp.async, ex2.f16x2 softmax, ones-MMA l).
//    Epilogue: out[i,o] = sum_c (O[i,c]/l_i) wo[o,c] + bo[o] + x[o,i] via MMA.
// ---------------------------------------------------------------------------
#define KROWB 144
#define VROWB 272
#define KBYTES (128 * KROWB)        // 18432
#define VBYTES (64 * VROWB)         // 17408
#define BUFB (KBYTES + VBYTES)      // 35840
#define WOROWB 144
#define OFF_WO (2 * BUFB)           // 71680
#define ATTN_SMEM (OFF_WO + 64 * WOROWB)   // 80896

__device__ __forceinline__ void prefetch_tile(char* smp, int s, int b, int jt, int tid) {
    // K: 128 rows x 128B. thread -> row j = tid>>1, half hf = tid&1 (64B)
    {
        int j = tid >> 1, hf = tid & 1;
        const __half* src = g_k + (size_t)(b * NNPOS + jt + j) * CC + hf * 32;
        uint32_t dst = (uint32_t)__cvta_generic_to_shared(smp + s * BUFB + j * KROWB + hf * 64);
#pragma unroll
        for (int u = 0; u < 4; u++) cpasync16(dst + u * 16, src + u * 8);
    }
    // V: 64 rows x 256B. thread -> row c = tid>>2, quarter q = tid&3 (64B)
    {
        int c = tid >> 2, q = tid & 3;
        const __half* src = g_v + (size_t)(b * CC + c) * NNPOS + jt + q * 32;
        uint32_t dst = (uint32_t)__cvta_generic_to_shared(smp + s * BUFB + KBYTES + c * VROWB + q * 64);
#pragma unroll
        for (int u = 0; u < 4; u++) cpasync16(dst + u * 16, src + u * 8);
    }
}

__global__ __launch_bounds__(256, 1) void attn_kernel(const float* __restrict__ wo,
                                                      const float* __restrict__ bo,
                                                      const float* __restrict__ x,
                                                      float* __restrict__ out) {
    extern __shared__ char smp[];
    int tid = threadIdx.x;
    int w = tid >> 5, lane = tid & 31;
    int b = blockIdx.y;
    int i0 = blockIdx.x * 128;
    int g = lane >> 2, t4 = lane & 3;

    // B-type ldmatrix.x4 lane offset pieces
    int laneRowB = (lane & 7) + ((lane & 16) >> 1);
    int laneKB   = (lane & 8) << 1;
    uint32_t loffK = (uint32_t)(laneRowB * KROWB + laneKB);
    uint32_t loffV = (uint32_t)(laneRowB * VROWB + laneKB);
    uint32_t smbase = (uint32_t)__cvta_generic_to_shared(smp);

    prefetch_tile(smp, 0, b, 0, tid);
    cpcommit();

    // Load wo (64x64 fp32) -> smem fp16 rows [o][c], stride WOROWB
    {
        int o = tid >> 2, qq = tid & 3;    // 16 c per thread
        const float* src = wo + o * 64 + qq * 16;
        uint32_t hx[8];
#pragma unroll
        for (int u = 0; u < 8; u++) {
            float2 f2 = *(const float2*)(src + u * 2);
            hx[u] = h2u(__floats2half2_rn(f2.x, f2.y));
        }
        char* dst = smp + OFF_WO + o * WOROWB + qq * 32;
        *(uint4*)dst = make_uint4(hx[0], hx[1], hx[2], hx[3]);
        *(uint4*)(dst + 16) = make_uint4(hx[4], hx[5], hx[6], hx[7]);
    }

    // Q A-fragments resident: qA[ks][0..3], ks = 0..3 (K=64)
    uint32_t qA[4][4];
    {
        size_t row0 = (size_t)(b * NNPOS + i0 + w * 16 + g) * CC;
        size_t row8 = row0 + 8 * CC;
#pragma unroll
        for (int ks = 0; ks < 4; ks++) {
            int col = 2 * t4 + 16 * ks;
            qA[ks][0] = *(const uint32_t*)(g_q + row0 + col);
            qA[ks][1] = *(const uint32_t*)(g_q + row8 + col);
            qA[ks][2] = *(const uint32_t*)(g_q + row0 + col + 8);
            qA[ks][3] = *(const uint32_t*)(g_q + row8 + col + 8);
        }
    }

    float oacc[8][4] = {};
    float lacc[4] = {};

    for (int tix = 0; tix < 32; tix++) {
        cpwait0();
        __syncthreads();
        if (tix < 31) { prefetch_tile(smp, (tix + 1) & 1, b, (tix + 1) * 128, tid); cpcommit(); }

        uint32_t kb = smbase + (uint32_t)((tix & 1) * BUFB) + loffK;
        uint32_t vb = smbase + (uint32_t)((tix & 1) * BUFB + KBYTES) + loffV;

        // ---- S = Q K^T : M=16 x N=128, K=64, ldsm double-buffered ----
        float sacc[16][4] = {};
        {
            uint32_t b4[2][4];
            ldsm4(b4[0], kb);
#pragma unroll
            for (int it = 0; it < 32; it++) {
                int ks = it >> 3, np = it & 7;
                int cur = it & 1;
                if (it < 31) {
                    int nx = it + 1;
                    ldsm4(b4[cur ^ 1], kb + (uint32_t)((nx & 7) * (16 * KROWB) + (nx >> 3) * 32));
                }
                mma16816(sacc[2 * np],     qA[ks], b4[cur][0], b4[cur][1]);
                mma16816(sacc[2 * np + 1], qA[ks], b4[cur][2], b4[cur][3]);
            }
        }

        // ---- p = 2^S (cvt + MUFU ex2.f16x2), l via ones-MMA, O += P V^T ----
        {
            uint32_t v4[2][4];
            ldsm4(v4[0], vb);
#pragma unroll
            for (int ks2 = 0; ks2 < 8; ks2++) {
                uint32_t pA[4];
                {
                    float* se = sacc[2 * ks2];
                    float* so = sacc[2 * ks2 + 1];
                    pA[0] = exp2_f16x2(se[0], se[1]);
                    pA[1] = exp2_f16x2(se[2], se[3]);
                    pA[2] = exp2_f16x2(so[0], so[1]);
                    pA[3] = exp2_f16x2(so[2], so[3]);
                }
                mma16816(lacc, pA, ONES2, ONES2);   // row-sums (all cols identical)
#pragma unroll
                for (int np = 0; np < 4; np++) {
                    int it = ks2 * 4 + np;
                    int cur = it & 1;
                    if (it < 31) {
                        int nx = it + 1;
                        ldsm4(v4[cur ^ 1], vb + (uint32_t)((nx & 3) * (16 * VROWB) + (nx >> 2) * 32));
                    }
                    mma16816(oacc[2 * np],     pA, v4[cur][0], v4[cur][1]);
                    mma16816(oacc[2 * np + 1], pA, v4[cur][2], v4[cur][3]);
                }
            }
        }
    }

    // ---- fused out-projection: out = (O/l) @ wo^T + bo + x ----
    float inv0 = 1.f / lacc[0], inv1 = 1.f / lacc[2];

    // O -> fp16 A-fragments (normalize during convert)
    uint32_t oA[4][4];
#pragma unroll
    for (int ks = 0; ks < 4; ks++) {
        oA[ks][0] = h2u(__floats2half2_rn(oacc[2 * ks][0] * inv0,     oacc[2 * ks][1] * inv0));
        oA[ks][1] = h2u(__floats2half2_rn(oacc[2 * ks][2] * inv1,     oacc[2 * ks][3] * inv1));
        oA[ks][2] = h2u(__floats2half2_rn(oacc[2 * ks + 1][0] * inv0, oacc[2 * ks + 1][1] * inv0));
        oA[ks][3] = h2u(__floats2half2_rn(oacc[2 * ks + 1][2] * inv1, oacc[2 * ks + 1][3] * inv1));
    }

    // dacc[i][o]: M=16 x N=64, K=64 against wo rows in smem
    float dacc[8][4] = {};
    {
        uint32_t wob = smbase + (uint32_t)OFF_WO + loffK;   // WOROWB == KROWB
#pragma unroll
        for (int it = 0; it < 16; it++) {
            int ks = it >> 2, np = it & 3;
            uint32_t b4[4];
            ldsm4(b4, wob + (uint32_t)(np * (16 * WOROWB) + ks * 32));
            mma16816(dacc[2 * np],     oA[ks], b4[0], b4[1]);
            mma16816(dacc[2 * np + 1], oA[ks], b4[2], b4[3]);
        }
    }

    // write out (B,C,N) fp32 with bias + residual
    int irow0 = i0 + w * 16 + g;
#pragma unroll
    for (int nt = 0; nt < 8; nt++) {
        int o = nt * 8 + 2 * t4;
        float b0v = __ldg(&bo[o]), b1v = __ldg(&bo[o + 1]);
        size_t a00 = (size_t)(b * CC + o) * NNPOS + irow0;
        size_t a10 = a00 + NNPOS;            // o+1
        out[a00]     = dacc[nt][0] + b0v + __ldg(&x[a00]);
        out[a10]     = dacc[nt][1] + b1v + __ldg(&x[a10]);
        out[a00 + 8] = dacc[nt][2] + b0v + __ldg(&x[a00 + 8]);
        out[a10 + 8] = dacc[nt][3] + b1v + __ldg(&x[a10 + 8]);
    }
}

// ---------------------------------------------------------------------------
extern "C" void kernel_launch(void* const* d_in, const int* in_sizes, int n_in,
                              void* d_out, int out_size) {
    (void)in_sizes; (void)n_in; (void)out_size;
    const float* x    = (const float*)d_in[0];
    const float* ln_g = (const float*)d_in[1];
    const float* ln_b = (const float*)d_in[2];
    const float* wq   = (const float*)d_in[3];
    const float* bq   = (const float*)d_in[4];
    const float* wk   = (const float*)d_in[5];
    const float* bk   = (const float*)d_in[6];
    const float* wv   = (const float*)d_in[7];
    const float* bv   = (const float*)d_in[8];
    const float* wo   = (const float*)d_in[9];
    const float* bo   = (const float*)d_in[10];
    float* out = (float*)d_out;

    ln_kernel<<<(BB * NNPOS) / 256, 256>>>(x, ln_g, ln_b);
    qproj_kernel<<<dim3(NNPOS / 64, BB), 256>>>(wq, bq);
    dwconv_kernel<<<dim3(NNPOS / 128, 4, BB), 128>>>(wk, bk, wv, bv);
    cudaFuncSetAttribute(attn_kernel, cudaFuncAttributeMaxDynamicSharedMemorySize, ATTN_SMEM);
    attn_kernel<<<dim3(NNPOS / 128, BB), 256, ATTN_SMEM>>>(wo, bo, x, out);
}

// round 9
// speedup vs baseline: 1.2828x; 1.0671x over previous
#include <cuda_runtime.h>
#include <cuda_fp16.h>
#include <cstdint>

#define BB 4
#define CC 64
#define NNPOS 4096
#define HH 64
#define WW 64

// Scratch (__device__ globals; no allocs allowed)
__device__ __half g_q[BB * NNPOS * CC];            // Q fp16 (B,N,C), x (0.125*log2e) folded
__device__ __half g_k[BB * NNPOS * CC];            // K fp16 (B,N,C)
__device__ __half g_v[BB * CC * NNPOS];            // V fp16 (B,C,N)

#define QSCALE 0.18033688011112293f   // 0.125 * log2(e)
#define ONES2 0x3C003C00u              // half2(1.0, 1.0)

// ---------------- helpers ----------------
__device__ __forceinline__ uint32_t h2u(__half2 h) { return *reinterpret_cast<uint32_t*>(&h); }

__device__ __forceinline__ void ldsm4(uint32_t* r, uint32_t addr) {
    asm volatile("ldmatrix.sync.aligned.m8n8.x4.shared.b16 {%0,%1,%2,%3}, [%4];"
                 : "=r"(r[0]), "=r"(r[1]), "=r"(r[2]), "=r"(r[3]) : "r"(addr));
}
__device__ __forceinline__ void mma16816(float* d, const uint32_t* a, uint32_t b0, uint32_t b1) {
    asm volatile("mma.sync.aligned.m16n8k16.row.col.f32.f16.f16.f32 "
                 "{%0,%1,%2,%3},{%4,%5,%6,%7},{%8,%9},{%0,%1,%2,%3};"
                 : "+f"(d[0]), "+f"(d[1]), "+f"(d[2]), "+f"(d[3])
                 : "r"(a[0]), "r"(a[1]), "r"(a[2]), "r"(a[3]), "r"(b0), "r"(b1));
}
__device__ __forceinline__ void cpasync16(uint32_t dst, const void* src) {
    asm volatile("cp.async.cg.shared.global [%0], [%1], 16;" :: "r"(dst), "l"(src));
}
__device__ __forceinline__ void cpcommit() { asm volatile("cp.async.commit_group;"); }
__device__ __forceinline__ void cpwait0()  { asm volatile("cp.async.wait_group 0;"); }

// p_f16x2 = 2^{slo, shi} via one cvt + one MUFU ex2 (pairwise)
__device__ __forceinline__ uint32_t exp2_f16x2(float slo, float shi) {
    uint32_t h, r;
    asm("cvt.rn.f16x2.f32 %0, %1, %2;" : "=r"(h) : "f"(shi), "f"(slo));
    asm("ex2.approx.f16x2 %0, %1;" : "=r"(r) : "r"(h));
    return r;
}

// ---------------------------------------------------------------------------
// 1) Fused prep: LN + qproj + dwconv(k,v). grid (32, B), 256 threads.
//    Tile = 2 image rows (+1 halo row each side). xn lives only in smem.
// ---------------------------------------------------------------------------
// dyn smem layout (bytes):
#define PR_WQT   0                      // fp32 [c][o]      16384
#define PR_WK    16384                  // fp32 [c*9]        2304
#define PR_WV    18688                  //                   2304
#define PR_BQ    20992                  // fp32 [64]          256
#define PR_BK    21248
#define PR_BV    21504
#define PR_XS    21760                  // fp16 [c][256]    32768
#define PREP_SMEM (PR_XS + 64 * 256 * 2)   // 54528

__global__ __launch_bounds__(256) void prep_kernel(
    const float* __restrict__ x,
    const float* __restrict__ ln_g, const float* __restrict__ ln_b,
    const float* __restrict__ wq, const float* __restrict__ bq,
    const float* __restrict__ wk, const float* __restrict__ bk,
    const float* __restrict__ wv, const float* __restrict__ bv)
{
    extern __shared__ char psm[];
    float* WqT = (float*)(psm + PR_WQT);
    float* Wk  = (float*)(psm + PR_WK);
    float* Wv  = (float*)(psm + PR_WV);
    float* Bq  = (float*)(psm + PR_BQ);
    float* Bk  = (float*)(psm + PR_BK);
    float* Bv  = (float*)(psm + PR_BV);
    __half* Xs = (__half*)(psm + PR_XS);

    int tid = threadIdx.x;
    int h0 = blockIdx.x * 2;
    int b = blockIdx.y;

    // stage weights
    for (int t = tid; t < 4096; t += 256) {
        int o = t >> 6, c = t & 63;
        WqT[c * 64 + o] = wq[t];          // wq[o][c] -> [c][o]
    }
    for (int t = tid; t < 576; t += 256) { Wk[t] = wk[t]; Wv[t] = wv[t]; }
    if (tid < 64) { Bq[tid] = bq[tid]; Bk[tid] = bk[tid]; Bv[tid] = bv[tid]; }

    // ---- Phase 1: LN of rows h0-1 .. h0+2 (zero pad outside) -> Xs[c][tid]
    {
        int hh = tid >> 6;              // 0..3
        int w  = tid & 63;
        int h = h0 - 1 + hh;
        if (h >= 0 && h < HH) {
            const float* xp = x + (size_t)b * CC * NNPOS + h * WW + w;
            float vals[CC];
            float s = 0.f;
#pragma unroll
            for (int c = 0; c < CC; c++) { vals[c] = xp[(size_t)c * NNPOS]; s += vals[c]; }
            float mu = s * (1.f / 64.f);
            float vs = 0.f;
#pragma unroll
            for (int c = 0; c < CC; c++) { float d = vals[c] - mu; vs += d * d; }
            float rstd = rsqrtf(vs * (1.f / 64.f) + 1e-5f);
#pragma unroll
            for (int c = 0; c < CC; c++)
                Xs[c * 256 + tid] = __float2half_rn((vals[c] - mu) * rstd * __ldg(&ln_g[c]) + __ldg(&ln_b[c]));
        } else {
#pragma unroll
            for (int c = 0; c < CC; c++) Xs[c * 256 + tid] = __ushort_as_half((unsigned short)0);
        }
    }
    __syncthreads();

    // ---- Phase 2: qproj. thread -> (pos p = tid>>1, o-half = (tid&1)*32)
    {
        int p = tid >> 1;               // 0..127 tile positions (rows h0, h0+1)
        int posIdx = 64 + p;
        int o0 = (tid & 1) * 32;
        float acc[32] = {};
#pragma unroll 8
        for (int c = 0; c < CC; c++) {
            float xv = __half2float(Xs[c * 256 + posIdx]);
            const float4* wrow = (const float4*)&WqT[c * 64 + o0];
#pragma unroll
            for (int u = 0; u < 8; u++) {
                float4 w4 = wrow[u];
                acc[u * 4 + 0] += w4.x * xv;
                acc[u * 4 + 1] += w4.y * xv;
                acc[u * 4 + 2] += w4.z * xv;
                acc[u * 4 + 3] += w4.w * xv;
            }
        }
        int gpos = h0 * WW + p;
        __half* qdst = g_q + (size_t)(b * NNPOS + gpos) * CC + o0;
        uint32_t hx[16];
#pragma unroll
        for (int j = 0; j < 16; j++) {
            float a0 = (acc[2 * j]     + Bq[o0 + 2 * j])     * QSCALE;
            float a1 = (acc[2 * j + 1] + Bq[o0 + 2 * j + 1]) * QSCALE;
            hx[j] = h2u(__floats2half2_rn(a0, a1));
        }
#pragma unroll
        for (int j = 0; j < 4; j++)
            *(uint4*)(qdst + j * 8) = make_uint4(hx[4 * j], hx[4 * j + 1], hx[4 * j + 2], hx[4 * j + 3]);
    }

    // ---- Phase 3: dwconv (reads Xs only; no extra sync needed)
#pragma unroll
    for (int r = 0; r < 2; r++) {
        int idx = tid + r * 256;        // 0..511
        int cg = idx >> 7;              // 0..3
        int p  = idx & 127;
        int hhp = 1 + (p >> 6);         // smem row 1 or 2
        int wp = p & 63;
        int gpos = (h0 + (p >> 6)) * WW + wp;
        uint32_t khp[8];
        uint32_t khprev = 0;
#pragma unroll
        for (int ci = 0; ci < 16; ci++) {
            int c = cg * 16 + ci;
            const __half* xrow = Xs + c * 256;
            const float* wkp = Wk + c * 9;
            const float* wvp = Wv + c * 9;
            float sk = Bk[c], sv = Bv[c];
#pragma unroll
            for (int dh = 0; dh < 3; dh++) {
                int hs = (hhp + dh - 1) * 64;
#pragma unroll
                for (int dw = 0; dw < 3; dw++) {
                    int ws = wp + dw - 1;
                    if (ws < 0 || ws >= WW) continue;
                    float xv = __half2float(xrow[hs + ws]);
                    sk += xv * wkp[dh * 3 + dw];
                    sv += xv * wvp[dh * 3 + dw];
                }
            }
            g_v[(size_t)(b * CC + c) * NNPOS + gpos] = __float2half_rn(sv);
            uint32_t hb = (uint32_t)__half_as_ushort(__float2half_rn(sk));
            if (ci & 1) khp[ci >> 1] = khprev | (hb << 16);
            else khprev = hb;
        }
        __half* kdst = g_k + (size_t)(b * NNPOS + gpos) * CC + cg * 16;
        *(uint4*)kdst       = make_uint4(khp[0], khp[1], khp[2], khp[3]);
        *(uint4*)(kdst + 8) = make_uint4(khp[4], khp[5], khp[6], khp[7]);
    }
}

// ---------------------------------------------------------------------------
// 2) HMMA flash attention + fused out-projection + bias + residual (R8 loop).
// ---------------------------------------------------------------------------
#define KROWB 144
#define VROWB 272
#define KBYTES (128 * KROWB)        // 18432
#define VBYTES (64 * VROWB)         // 17408
#define BUFB (KBYTES + VBYTES)      // 35840
#define WOROWB 144
#define OFF_WO (2 * BUFB)           // 71680
#define ATTN_SMEM (OFF_WO + 64 * WOROWB)   // 80896

__device__ __forceinline__ void prefetch_tile(char* smp, int s, int b, int jt, int tid) {
    {
        int j = tid >> 1, hf = tid & 1;
        const __half* src = g_k + (size_t)(b * NNPOS + jt + j) * CC + hf * 32;
        uint32_t dst = (uint32_t)__cvta_generic_to_shared(smp + s * BUFB + j * KROWB + hf * 64);
#pragma unroll
        for (int u = 0; u < 4; u++) cpasync16(dst + u * 16, src + u * 8);
    }
    {
        int c = tid >> 2, q = tid & 3;
        const __half* src = g_v + (size_t)(b * CC + c) * NNPOS + jt + q * 32;
        uint32_t dst = (uint32_t)__cvta_generic_to_shared(smp + s * BUFB + KBYTES + c * VROWB + q * 64);
#pragma unroll
        for (int u = 0; u < 4; u++) cpasync16(dst + u * 16, src + u * 8);
    }
}

__global__ __launch_bounds__(256, 1) void attn_kernel(const float* __restrict__ wo,
                                                      const float* __restrict__ bo,
                                                      const float* __restrict__ x,
                                                      float* __restrict__ out) {
    extern __shared__ char smp[];
    int tid = threadIdx.x;
    int w = tid >> 5, lane = tid & 31;
    int b = blockIdx.y;
    int i0 = blockIdx.x * 128;
    int g = lane >> 2, t4 = lane & 3;

    int laneRowB = (lane & 7) + ((lane & 16) >> 1);
    int laneKB   = (lane & 8) << 1;
    uint32_t loffK = (uint32_t)(laneRowB * KROWB + laneKB);
    uint32_t loffV = (uint32_t)(laneRowB * VROWB + laneKB);
    uint32_t smbase = (uint32_t)__cvta_generic_to_shared(smp);

    prefetch_tile(smp, 0, b, 0, tid);
    cpcommit();

    // Load wo (64x64 fp32) -> smem fp16 rows [o][c], stride WOROWB
    {
        int o = tid >> 2, qq = tid & 3;
        const float* src = wo + o * 64 + qq * 16;
        uint32_t hx[8];
#pragma unroll
        for (int u = 0; u < 8; u++) {
            float2 f2 = *(const float2*)(src + u * 2);
            hx[u] = h2u(__floats2half2_rn(f2.x, f2.y));
        }
        char* dst = smp + OFF_WO + o * WOROWB + qq * 32;
        *(uint4*)dst = make_uint4(hx[0], hx[1], hx[2], hx[3]);
        *(uint4*)(dst + 16) = make_uint4(hx[4], hx[5], hx[6], hx[7]);
    }

    uint32_t qA[4][4];
    {
        size_t row0 = (size_t)(b * NNPOS + i0 + w * 16 + g) * CC;
        size_t row8 = row0 + 8 * CC;
#pragma unroll
        for (int ks = 0; ks < 4; ks++) {
            int col = 2 * t4 + 16 * ks;
            qA[ks][0] = *(const uint32_t*)(g_q + row0 + col);
            qA[ks][1] = *(const uint32_t*)(g_q + row8 + col);
            qA[ks][2] = *(const uint32_t*)(g_q + row0 + col + 8);
            qA[ks][3] = *(const uint32_t*)(g_q + row8 + col + 8);
        }
    }

    float oacc[8][4] = {};
    float lacc[4] = {};

    for (int tix = 0; tix < 32; tix++) {
        cpwait0();
        __syncthreads();
        if (tix < 31) { prefetch_tile(smp, (tix + 1) & 1, b, (tix + 1) * 128, tid); cpcommit(); }

        uint32_t kb = smbase + (uint32_t)((tix & 1) * BUFB) + loffK;
        uint32_t vb = smbase + (uint32_t)((tix & 1) * BUFB + KBYTES) + loffV;

        float sacc[16][4] = {};
        {
            uint32_t b4[2][4];
            ldsm4(b4[0], kb);
#pragma unroll
            for (int it = 0; it < 32; it++) {
                int ks = it >> 3, np = it & 7;
                int cur = it & 1;
                if (it < 31) {
                    int nx = it + 1;
                    ldsm4(b4[cur ^ 1], kb + (uint32_t)((nx & 7) * (16 * KROWB) + (nx >> 3) * 32));
                }
                mma16816(sacc[2 * np],     qA[ks], b4[cur][0], b4[cur][1]);
                mma16816(sacc[2 * np + 1], qA[ks], b4[cur][2], b4[cur][3]);
            }
        }
        {
            uint32_t v4[2][4];
            ldsm4(v4[0], vb);
#pragma unroll
            for (int ks2 = 0; ks2 < 8; ks2++) {
                uint32_t pA[4];
                {
                    float* se = sacc[2 * ks2];
                    float* so = sacc[2 * ks2 + 1];
                    pA[0] = exp2_f16x2(se[0], se[1]);
                    pA[1] = exp2_f16x2(se[2], se[3]);
                    pA[2] = exp2_f16x2(so[0], so[1]);
                    pA[3] = exp2_f16x2(so[2], so[3]);
                }
                mma16816(lacc, pA, ONES2, ONES2);
#pragma unroll
                for (int np = 0; np < 4; np++) {
                    int it = ks2 * 4 + np;
                    int cur = it & 1;
                    if (it < 31) {
                        int nx = it + 1;
                        ldsm4(v4[cur ^ 1], vb + (uint32_t)((nx & 3) * (16 * VROWB) + (nx >> 2) * 32));
                    }
                    mma16816(oacc[2 * np],     pA, v4[cur][0], v4[cur][1]);
                    mma16816(oacc[2 * np + 1], pA, v4[cur][2], v4[cur][3]);
                }
            }
        }
    }

    // fused out-projection: out = (O/l) @ wo^T + bo + x
    float inv0 = 1.f / lacc[0], inv1 = 1.f / lacc[2];
    uint32_t oA[4][4];
#pragma unroll
    for (int ks = 0; ks < 4; ks++) {
        oA[ks][0] = h2u(__floats2half2_rn(oacc[2 * ks][0] * inv0,     oacc[2 * ks][1] * inv0));
        oA[ks][1] = h2u(__floats2half2_rn(oacc[2 * ks][2] * inv1,     oacc[2 * ks][3] * inv1));
        oA[ks][2] = h2u(__floats2half2_rn(oacc[2 * ks + 1][0] * inv0, oacc[2 * ks + 1][1] * inv0));
        oA[ks][3] = h2u(__floats2half2_rn(oacc[2 * ks + 1][2] * inv1, oacc[2 * ks + 1][3] * inv1));
    }
    float dacc[8][4] = {};
    {
        uint32_t wob = smbase + (uint32_t)OFF_WO + loffK;
#pragma unroll
        for (int it = 0; it < 16; it++) {
            int ks = it >> 2, np = it & 3;
            uint32_t b4[4];
            ldsm4(b4, wob + (uint32_t)(np * (16 * WOROWB) + ks * 32));
            mma16816(dacc[2 * np],     oA[ks], b4[0], b4[1]);
            mma16816(dacc[2 * np + 1], oA[ks], b4[2], b4[3]);
        }
    }
    int irow0 = i0 + w * 16 + g;
#pragma unroll
    for (int nt = 0; nt < 8; nt++) {
        int o = nt * 8 + 2 * t4;
        float b0v = __ldg(&bo[o]), b1v = __ldg(&bo[o + 1]);
        size_t a00 = (size_t)(b * CC + o) * NNPOS + irow0;
        size_t a10 = a00 + NNPOS;
        out[a00]     = dacc[nt][0] + b0v + __ldg(&x[a00]);
        out[a10]     = dacc[nt][1] + b1v + __ldg(&x[a10]);
        out[a00 + 8] = dacc[nt][2] + b0v + __ldg(&x[a00 + 8]);
        out[a10 + 8] = dacc[nt][3] + b1v + __ldg(&x[a10 + 8]);
    }
}

// ---------------------------------------------------------------------------
extern "C" void kernel_launch(void* const* d_in, const int* in_sizes, int n_in,
                              void* d_out, int out_size) {
    (void)in_sizes; (void)n_in; (void)out_size;
    const float* x    = (const float*)d_in[0];
    const float* ln_g = (const float*)d_in[1];
    const float* ln_b = (const float*)d_in[2];
    const float* wq   = (const float*)d_in[3];
    const float* bq   = (const float*)d_in[4];
    const float* wk   = (const float*)d_in[5];
    const float* bk   = (const float*)d_in[6];
    const float* wv   = (const float*)d_in[7];
    const float* bv   = (const float*)d_in[8];
    const float* wo   = (const float*)d_in[9];
    const float* bo   = (const float*)d_in[10];
    float* out = (float*)d_out;

    cudaFuncSetAttribute(prep_kernel, cudaFuncAttributeMaxDynamicSharedMemorySize, PREP_SMEM);
    prep_kernel<<<dim3(32, BB), 256, PREP_SMEM>>>(x, ln_g, ln_b, wq, bq, wk, bk, wv, bv);
    cudaFuncSetAttribute(attn_kernel, cudaFuncAttributeMaxDynamicSharedMemorySize, ATTN_SMEM);
    attn_kernel<<<dim3(NNPOS / 128, BB), 256, ATTN_SMEM>>>(wo, bo, x, out);
}

// round 10
// speedup vs baseline: 1.3343x; 1.0402x over previous
#include <cuda_runtime.h>
#include <cuda_fp16.h>
#include <cstdint>

#define BB 4
#define CC 64
#define NNPOS 4096
#define HH 64
#define WW 64

// Scratch (__device__ globals; no allocs allowed)
__device__ __half g_q[BB * NNPOS * CC];            // Q fp16 (B,N,C), x (0.125*log2e) folded
__device__ __half g_k[BB * NNPOS * CC];            // K fp16 (B,N,C)
__device__ __half g_v[BB * CC * NNPOS];            // V fp16 (B,C,N)

#define QSCALE 0.18033688011112293f   // 0.125 * log2(e)
#define ONES2 0x3C003C00u              // half2(1.0, 1.0)

// ---------------- helpers ----------------
__device__ __forceinline__ uint32_t h2u(__half2 h) { return *reinterpret_cast<uint32_t*>(&h); }

__device__ __forceinline__ void ldsm4(uint32_t* r, uint32_t addr) {
    asm volatile("ldmatrix.sync.aligned.m8n8.x4.shared.b16 {%0,%1,%2,%3}, [%4];"
                 : "=r"(r[0]), "=r"(r[1]), "=r"(r[2]), "=r"(r[3]) : "r"(addr));
}
__device__ __forceinline__ void mma16816(float* d, const uint32_t* a, uint32_t b0, uint32_t b1) {
    asm volatile("mma.sync.aligned.m16n8k16.row.col.f32.f16.f16.f32 "
                 "{%0,%1,%2,%3},{%4,%5,%6,%7},{%8,%9},{%0,%1,%2,%3};"
                 : "+f"(d[0]), "+f"(d[1]), "+f"(d[2]), "+f"(d[3])
                 : "r"(a[0]), "r"(a[1]), "r"(a[2]), "r"(a[3]), "r"(b0), "r"(b1));
}
// fp16-accumulate HMMA: D fragment {d0,d1} = packed col-pairs (rows g, g+8)
__device__ __forceinline__ void mma16816h(uint32_t* d, const uint32_t* a, uint32_t b0, uint32_t b1) {
    asm volatile("mma.sync.aligned.m16n8k16.row.col.f16.f16.f16.f16 "
                 "{%0,%1},{%2,%3,%4,%5},{%6,%7},{%0,%1};"
                 : "+r"(d[0]), "+r"(d[1])
                 : "r"(a[0]), "r"(a[1]), "r"(a[2]), "r"(a[3]), "r"(b0), "r"(b1));
}
__device__ __forceinline__ void cpasync16(uint32_t dst, const void* src) {
    asm volatile("cp.async.cg.shared.global [%0], [%1], 16;" :: "r"(dst), "l"(src));
}
__device__ __forceinline__ void cpcommit() { asm volatile("cp.async.commit_group;"); }
__device__ __forceinline__ void cpwait0()  { asm volatile("cp.async.wait_group 0;"); }

// 2^x elementwise on packed f16x2 (MUFU, pairwise)
__device__ __forceinline__ uint32_t ex2h2(uint32_t s) {
    uint32_t r;
    asm("ex2.approx.f16x2 %0, %1;" : "=r"(r) : "r"(s));
    return r;
}

// ---------------------------------------------------------------------------
// 1) Fused prep: LN + qproj + dwconv(k,v). grid (32, B), 256 threads.
// ---------------------------------------------------------------------------
#define PR_WQT   0                      // fp32 [c][o]      16384
#define PR_WK    16384                  // fp32 [c*9]        2304
#define PR_WV    18688                  //                   2304
#define PR_BQ    20992                  // fp32 [64]          256
#define PR_BK    21248
#define PR_BV    21504
#define PR_XS    21760                  // fp16 [c][256]    32768
#define PREP_SMEM (PR_XS + 64 * 256 * 2)   // 54528

__global__ __launch_bounds__(256) void prep_kernel(
    const float* __restrict__ x,
    const float* __restrict__ ln_g, const float* __restrict__ ln_b,
    const float* __restrict__ wq, const float* __restrict__ bq,
    const float* __restrict__ wk, const float* __restrict__ bk,
    const float* __restrict__ wv, const float* __restrict__ bv)
{
    extern __shared__ char psm[];
    float* WqT = (float*)(psm + PR_WQT);
    float* Wk  = (float*)(psm + PR_WK);
    float* Wv  = (float*)(psm + PR_WV);
    float* Bq  = (float*)(psm + PR_BQ);
    float* Bk  = (float*)(psm + PR_BK);
    float* Bv  = (float*)(psm + PR_BV);
    __half* Xs = (__half*)(psm + PR_XS);

    int tid = threadIdx.x;
    int h0 = blockIdx.x * 2;
    int b = blockIdx.y;

    for (int t = tid; t < 4096; t += 256) {
        int o = t >> 6, c = t & 63;
        WqT[c * 64 + o] = wq[t];
    }
    for (int t = tid; t < 576; t += 256) { Wk[t] = wk[t]; Wv[t] = wv[t]; }
    if (tid < 64) { Bq[tid] = bq[tid]; Bk[tid] = bk[tid]; Bv[tid] = bv[tid]; }

    // Phase 1: LN rows h0-1 .. h0+2 (zero pad) -> Xs[c][tid]
    {
        int hh = tid >> 6;
        int w  = tid & 63;
        int h = h0 - 1 + hh;
        if (h >= 0 && h < HH) {
            const float* xp = x + (size_t)b * CC * NNPOS + h * WW + w;
            float vals[CC];
            float s = 0.f;
#pragma unroll
            for (int c = 0; c < CC; c++) { vals[c] = xp[(size_t)c * NNPOS]; s += vals[c]; }
            float mu = s * (1.f / 64.f);
            float vs = 0.f;
#pragma unroll
            for (int c = 0; c < CC; c++) { float d = vals[c] - mu; vs += d * d; }
            float rstd = rsqrtf(vs * (1.f / 64.f) + 1e-5f);
#pragma unroll
            for (int c = 0; c < CC; c++)
                Xs[c * 256 + tid] = __float2half_rn((vals[c] - mu) * rstd * __ldg(&ln_g[c]) + __ldg(&ln_b[c]));
        } else {
#pragma unroll
            for (int c = 0; c < CC; c++) Xs[c * 256 + tid] = __ushort_as_half((unsigned short)0);
        }
    }
    __syncthreads();

    // Phase 2: qproj
    {
        int p = tid >> 1;
        int posIdx = 64 + p;
        int o0 = (tid & 1) * 32;
        float acc[32] = {};
#pragma unroll 8
        for (int c = 0; c < CC; c++) {
            float xv = __half2float(Xs[c * 256 + posIdx]);
            const float4* wrow = (const float4*)&WqT[c * 64 + o0];
#pragma unroll
            for (int u = 0; u < 8; u++) {
                float4 w4 = wrow[u];
                acc[u * 4 + 0] += w4.x * xv;
                acc[u * 4 + 1] += w4.y * xv;
                acc[u * 4 + 2] += w4.z * xv;
                acc[u * 4 + 3] += w4.w * xv;
            }
        }
        int gpos = h0 * WW + p;
        __half* qdst = g_q + (size_t)(b * NNPOS + gpos) * CC + o0;
        uint32_t hx[16];
#pragma unroll
        for (int j = 0; j < 16; j++) {
            float a0 = (acc[2 * j]     + Bq[o0 + 2 * j])     * QSCALE;
            float a1 = (acc[2 * j + 1] + Bq[o0 + 2 * j + 1]) * QSCALE;
            hx[j] = h2u(__floats2half2_rn(a0, a1));
        }
#pragma unroll
        for (int j = 0; j < 4; j++)
            *(uint4*)(qdst + j * 8) = make_uint4(hx[4 * j], hx[4 * j + 1], hx[4 * j + 2], hx[4 * j + 3]);
    }

    // Phase 3: dwconv
#pragma unroll
    for (int r = 0; r < 2; r++) {
        int idx = tid + r * 256;
        int cg = idx >> 7;
        int p  = idx & 127;
        int hhp = 1 + (p >> 6);
        int wp = p & 63;
        int gpos = (h0 + (p >> 6)) * WW + wp;
        uint32_t khp[8];
        uint32_t khprev = 0;
#pragma unroll
        for (int ci = 0; ci < 16; ci++) {
            int c = cg * 16 + ci;
            const __half* xrow = Xs + c * 256;
            const float* wkp = Wk + c * 9;
            const float* wvp = Wv + c * 9;
            float sk = Bk[c], sv = Bv[c];
#pragma unroll
            for (int dh = 0; dh < 3; dh++) {
                int hs = (hhp + dh - 1) * 64;
#pragma unroll
                for (int dw = 0; dw < 3; dw++) {
                    int ws = wp + dw - 1;
                    if (ws < 0 || ws >= WW) continue;
                    float xv = __half2float(xrow[hs + ws]);
                    sk += xv * wkp[dh * 3 + dw];
                    sv += xv * wvp[dh * 3 + dw];
                }
            }
            g_v[(size_t)(b * CC + c) * NNPOS + gpos] = __float2half_rn(sv);
            uint32_t hb = (uint32_t)__half_as_ushort(__float2half_rn(sk));
            if (ci & 1) khp[ci >> 1] = khprev | (hb << 16);
            else khprev = hb;
        }
        __half* kdst = g_k + (size_t)(b * NNPOS + gpos) * CC + cg * 16;
        *(uint4*)kdst       = make_uint4(khp[0], khp[1], khp[2], khp[3]);
        *(uint4*)(kdst + 8) = make_uint4(khp[4], khp[5], khp[6], khp[7]);
    }
}

// ---------------------------------------------------------------------------
// 2) HMMA flash attention (fp16-acc S) + fused out-proj + bias + residual.
// ---------------------------------------------------------------------------
#define KROWB 144
#define VROWB 272
#define KBYTES (128 * KROWB)        // 18432
#define VBYTES (64 * VROWB)         // 17408
#define BUFB (KBYTES + VBYTES)      // 35840
#define WOROWB 144
#define OFF_WO (2 * BUFB)           // 71680
#define ATTN_SMEM (OFF_WO + 64 * WOROWB)   // 80896

__device__ __forceinline__ void prefetch_tile(char* smp, int s, int b, int jt, int tid) {
    {
        int j = tid >> 1, hf = tid & 1;
        const __half* src = g_k + (size_t)(b * NNPOS + jt + j) * CC + hf * 32;
        uint32_t dst = (uint32_t)__cvta_generic_to_shared(smp + s * BUFB + j * KROWB + hf * 64);
#pragma unroll
        for (int u = 0; u < 4; u++) cpasync16(dst + u * 16, src + u * 8);
    }
    {
        int c = tid >> 2, q = tid & 3;
        const __half* src = g_v + (size_t)(b * CC + c) * NNPOS + jt + q * 32;
        uint32_t dst = (uint32_t)__cvta_generic_to_shared(smp + s * BUFB + KBYTES + c * VROWB + q * 64);
#pragma unroll
        for (int u = 0; u < 4; u++) cpasync16(dst + u * 16, src + u * 8);
    }
}

__global__ __launch_bounds__(256, 1) void attn_kernel(const float* __restrict__ wo,
                                                      const float* __restrict__ bo,
                                                      const float* __restrict__ x,
                                                      float* __restrict__ out) {
    extern __shared__ char smp[];
    int tid = threadIdx.x;
    int w = tid >> 5, lane = tid & 31;
    int b = blockIdx.y;
    int i0 = blockIdx.x * 128;
    int g = lane >> 2, t4 = lane & 3;

    int laneRowB = (lane & 7) + ((lane & 16) >> 1);
    int laneKB   = (lane & 8) << 1;
    uint32_t loffK = (uint32_t)(laneRowB * KROWB + laneKB);
    uint32_t loffV = (uint32_t)(laneRowB * VROWB + laneKB);
    uint32_t smbase = (uint32_t)__cvta_generic_to_shared(smp);

    prefetch_tile(smp, 0, b, 0, tid);
    cpcommit();

    // wo (64x64 fp32) -> smem fp16 [o][c], stride WOROWB
    {
        int o = tid >> 2, qq = tid & 3;
        const float* src = wo + o * 64 + qq * 16;
        uint32_t hx[8];
#pragma unroll
        for (int u = 0; u < 8; u++) {
            float2 f2 = *(const float2*)(src + u * 2);
            hx[u] = h2u(__floats2half2_rn(f2.x, f2.y));
        }
        char* dst = smp + OFF_WO + o * WOROWB + qq * 32;
        *(uint4*)dst = make_uint4(hx[0], hx[1], hx[2], hx[3]);
        *(uint4*)(dst + 16) = make_uint4(hx[4], hx[5], hx[6], hx[7]);
    }

    uint32_t qA[4][4];
    {
        size_t row0 = (size_t)(b * NNPOS + i0 + w * 16 + g) * CC;
        size_t row8 = row0 + 8 * CC;
#pragma unroll
        for (int ks = 0; ks < 4; ks++) {
            int col = 2 * t4 + 16 * ks;
            qA[ks][0] = *(const uint32_t*)(g_q + row0 + col);
            qA[ks][1] = *(const uint32_t*)(g_q + row8 + col);
            qA[ks][2] = *(const uint32_t*)(g_q + row0 + col + 8);
            qA[ks][3] = *(const uint32_t*)(g_q + row8 + col + 8);
        }
    }

    float oacc[8][4] = {};
    float lacc[4] = {};

    for (int tix = 0; tix < 32; tix++) {
        cpwait0();
        __syncthreads();
        if (tix < 31) { prefetch_tile(smp, (tix + 1) & 1, b, (tix + 1) * 128, tid); cpcommit(); }

        uint32_t kb = smbase + (uint32_t)((tix & 1) * BUFB) + loffK;
        uint32_t vb = smbase + (uint32_t)((tix & 1) * BUFB + KBYTES) + loffV;

        // ---- S = Q K^T in fp16 accumulate: sacc16[nt] = packed col-pair regs ----
        uint32_t sacc16[16][2];
#pragma unroll
        for (int i = 0; i < 16; i++) { sacc16[i][0] = 0u; sacc16[i][1] = 0u; }
        {
            uint32_t b4[2][4];
            ldsm4(b4[0], kb);
#pragma unroll
            for (int it = 0; it < 32; it++) {
                int ks = it >> 3, np = it & 7;
                int cur = it & 1;
                if (it < 31) {
                    int nx = it + 1;
                    ldsm4(b4[cur ^ 1], kb + (uint32_t)((nx & 7) * (16 * KROWB) + (nx >> 3) * 32));
                }
                mma16816h(sacc16[2 * np],     qA[ks], b4[cur][0], b4[cur][1]);
                mma16816h(sacc16[2 * np + 1], qA[ks], b4[cur][2], b4[cur][3]);
            }
        }

        // ---- p = 2^S directly on fp16 regs; l via ones-MMA; O += P V^T ----
        {
            uint32_t v4[2][4];
            ldsm4(v4[0], vb);
#pragma unroll
            for (int ks2 = 0; ks2 < 8; ks2++) {
                uint32_t pA[4];
                pA[0] = ex2h2(sacc16[2 * ks2][0]);
                pA[1] = ex2h2(sacc16[2 * ks2][1]);
                pA[2] = ex2h2(sacc16[2 * ks2 + 1][0]);
                pA[3] = ex2h2(sacc16[2 * ks2 + 1][1]);
                mma16816(lacc, pA, ONES2, ONES2);
#pragma unroll
                for (int np = 0; np < 4; np++) {
                    int it = ks2 * 4 + np;
                    int cur = it & 1;
                    if (it < 31) {
                        int nx = it + 1;
                        ldsm4(v4[cur ^ 1], vb + (uint32_t)((nx & 3) * (16 * VROWB) + (nx >> 2) * 32));
                    }
                    mma16816(oacc[2 * np],     pA, v4[cur][0], v4[cur][1]);
                    mma16816(oacc[2 * np + 1], pA, v4[cur][2], v4[cur][3]);
                }
            }
        }
    }

    // fused out-projection: out = (O/l) @ wo^T + bo + x
    float inv0 = 1.f / lacc[0], inv1 = 1.f / lacc[2];
    uint32_t oA[4][4];
#pragma unroll
    for (int ks = 0; ks < 4; ks++) {
        oA[ks][0] = h2u(__floats2half2_rn(oacc[2 * ks][0] * inv0,     oacc[2 * ks][1] * inv0));
        oA[ks][1] = h2u(__floats2half2_rn(oacc[2 * ks][2] * inv1,     oacc[2 * ks][3] * inv1));
        oA[ks][2] = h2u(__floats2half2_rn(oacc[2 * ks + 1][0] * inv0, oacc[2 * ks + 1][1] * inv0));
        oA[ks][3] = h2u(__floats2half2_rn(oacc[2 * ks + 1][2] * inv1, oacc[2 * ks + 1][3] * inv1));
    }
    float dacc[8][4] = {};
    {
        uint32_t wob = smbase + (uint32_t)OFF_WO + loffK;
#pragma unroll
        for (int it = 0; it < 16; it++) {
            int ks = it >> 2, np = it & 3;
            uint32_t b4[4];
            ldsm4(b4, wob + (uint32_t)(np * (16 * WOROWB) + ks * 32));
            mma16816(dacc[2 * np],     oA[ks], b4[0], b4[1]);
            mma16816(dacc[2 * np + 1], oA[ks], b4[2], b4[3]);
        }
    }
    int irow0 = i0 + w * 16 + g;
#pragma unroll
    for (int nt = 0; nt < 8; nt++) {
        int o = nt * 8 + 2 * t4;
        float b0v = __ldg(&bo[o]), b1v = __ldg(&bo[o + 1]);
        size_t a00 = (size_t)(b * CC + o) * NNPOS + irow0;
        size_t a10 = a00 + NNPOS;
        out[a00]     = dacc[nt][0] + b0v + __ldg(&x[a00]);
        out[a10]     = dacc[nt][1] + b1v + __ldg(&x[a10]);
        out[a00 + 8] = dacc[nt][2] + b0v + __ldg(&x[a00 + 8]);
        out[a10 + 8] = dacc[nt][3] + b1v + __ldg(&x[a10 + 8]);
    }
}

// ---------------------------------------------------------------------------
extern "C" void kernel_launch(void* const* d_in, const int* in_sizes, int n_in,
                              void* d_out, int out_size) {
    (void)in_sizes; (void)n_in; (void)out_size;
    const float* x    = (const float*)d_in[0];
    const float* ln_g = (const float*)d_in[1];
    const float* ln_b = (const float*)d_in[2];
    const float* wq   = (const float*)d_in[3];
    const float* bq   = (const float*)d_in[4];
    const float* wk   = (const float*)d_in[5];
    const float* bk   = (const float*)d_in[6];
    const float* wv   = (const float*)d_in[7];
    const float* bv   = (const float*)d_in[8];
    const float* wo   = (const float*)d_in[9];
    const float* bo   = (const float*)d_in[10];
    float* out = (float*)d_out;

    cudaFuncSetAttribute(prep_kernel, cudaFuncAttributeMaxDynamicSharedMemorySize, PREP_SMEM);
    prep_kernel<<<dim3(32, BB), 256, PREP_SMEM>>>(x, ln_g, ln_b, wq, bq, wk, bk, wv, bv);
    cudaFuncSetAttribute(attn_kernel, cudaFuncAttributeMaxDynamicSharedMemorySize, ATTN_SMEM);
    attn_kernel<<<dim3(NNPOS / 128, BB), 256, ATTN_SMEM>>>(wo, bo, x, out);
}

// round 11
// speedup vs baseline: 1.3380x; 1.0028x over previous
#include <cuda_runtime.h>
#include <cuda_fp16.h>
#include <cstdint>

#define BB 4
#define CC 64
#define NNPOS 4096
#define HH 64
#define WW 64

// Scratch (__device__ globals; no allocs allowed)
__device__ __half g_q[BB * NNPOS * CC];            // Q fp16 (B,N,C), x (0.125*log2e) folded
__device__ __half g_k[BB * NNPOS * CC];            // K fp16 (B,N,C)
__device__ __half g_v[BB * CC * NNPOS];            // V fp16 (B,C,N)
__device__ float  g_po[2 * BB * NNPOS * CC];       // partial O per key-half (B,N,C) fp32
__device__ float  g_pl[2 * BB * NNPOS];            // partial l per key-half

#define QSCALE 0.18033688011112293f   // 0.125 * log2(e)
#define ONES2 0x3C003C00u              // half2(1.0, 1.0)

// ---------------- helpers ----------------
__device__ __forceinline__ uint32_t h2u(__half2 h) { return *reinterpret_cast<uint32_t*>(&h); }

__device__ __forceinline__ void ldsm4(uint32_t* r, uint32_t addr) {
    asm volatile("ldmatrix.sync.aligned.m8n8.x4.shared.b16 {%0,%1,%2,%3}, [%4];"
                 : "=r"(r[0]), "=r"(r[1]), "=r"(r[2]), "=r"(r[3]) : "r"(addr));
}
__device__ __forceinline__ void mma16816(float* d, const uint32_t* a, uint32_t b0, uint32_t b1) {
    asm volatile("mma.sync.aligned.m16n8k16.row.col.f32.f16.f16.f32 "
                 "{%0,%1,%2,%3},{%4,%5,%6,%7},{%8,%9},{%0,%1,%2,%3};"
                 : "+f"(d[0]), "+f"(d[1]), "+f"(d[2]), "+f"(d[3])
                 : "r"(a[0]), "r"(a[1]), "r"(a[2]), "r"(a[3]), "r"(b0), "r"(b1));
}
// fp16-accumulate HMMA (same tensor rate; saves cvt + regs in S phase)
__device__ __forceinline__ void mma16816h(uint32_t* d, const uint32_t* a, uint32_t b0, uint32_t b1) {
    asm volatile("mma.sync.aligned.m16n8k16.row.col.f16.f16.f16.f16 "
                 "{%0,%1},{%2,%3,%4,%5},{%6,%7},{%0,%1};"
                 : "+r"(d[0]), "+r"(d[1])
                 : "r"(a[0]), "r"(a[1]), "r"(a[2]), "r"(a[3]), "r"(b0), "r"(b1));
}
__device__ __forceinline__ void cpasync16(uint32_t dst, const void* src) {
    asm volatile("cp.async.cg.shared.global [%0], [%1], 16;" :: "r"(dst), "l"(src));
}
__device__ __forceinline__ void cpcommit() { asm volatile("cp.async.commit_group;"); }
__device__ __forceinline__ void cpwait0()  { asm volatile("cp.async.wait_group 0;"); }

// 2^x elementwise on packed f16x2 (MUFU, pairwise)
__device__ __forceinline__ uint32_t ex2h2(uint32_t s) {
    uint32_t r;
    asm("ex2.approx.f16x2 %0, %1;" : "=r"(r) : "r"(s));
    return r;
}

// ---------------------------------------------------------------------------
// 1) Fused prep: LN + qproj + dwconv(k,v). grid (32, B), 256 threads.
// ---------------------------------------------------------------------------
#define PR_WQT   0
#define PR_WK    16384
#define PR_WV    18688
#define PR_BQ    20992
#define PR_BK    21248
#define PR_BV    21504
#define PR_XS    21760
#define PREP_SMEM (PR_XS + 64 * 256 * 2)   // 54528

__global__ __launch_bounds__(256) void prep_kernel(
    const float* __restrict__ x,
    const float* __restrict__ ln_g, const float* __restrict__ ln_b,
    const float* __restrict__ wq, const float* __restrict__ bq,
    const float* __restrict__ wk, const float* __restrict__ bk,
    const float* __restrict__ wv, const float* __restrict__ bv)
{
    extern __shared__ char psm[];
    float* WqT = (float*)(psm + PR_WQT);
    float* Wk  = (float*)(psm + PR_WK);
    float* Wv  = (float*)(psm + PR_WV);
    float* Bq  = (float*)(psm + PR_BQ);
    float* Bk  = (float*)(psm + PR_BK);
    float* Bv  = (float*)(psm + PR_BV);
    __half* Xs = (__half*)(psm + PR_XS);

    int tid = threadIdx.x;
    int h0 = blockIdx.x * 2;
    int b = blockIdx.y;

    for (int t = tid; t < 4096; t += 256) {
        int o = t >> 6, c = t & 63;
        WqT[c * 64 + o] = wq[t];
    }
    for (int t = tid; t < 576; t += 256) { Wk[t] = wk[t]; Wv[t] = wv[t]; }
    if (tid < 64) { Bq[tid] = bq[tid]; Bk[tid] = bk[tid]; Bv[tid] = bv[tid]; }

    // Phase 1: LN rows h0-1 .. h0+2 (zero pad) -> Xs[c][tid]
    {
        int hh = tid >> 6;
        int w  = tid & 63;
        int h = h0 - 1 + hh;
        if (h >= 0 && h < HH) {
            const float* xp = x + (size_t)b * CC * NNPOS + h * WW + w;
            float vals[CC];
            float s = 0.f;
#pragma unroll
            for (int c = 0; c < CC; c++) { vals[c] = xp[(size_t)c * NNPOS]; s += vals[c]; }
            float mu = s * (1.f / 64.f);
            float vs = 0.f;
#pragma unroll
            for (int c = 0; c < CC; c++) { float d = vals[c] - mu; vs += d * d; }
            float rstd = rsqrtf(vs * (1.f / 64.f) + 1e-5f);
#pragma unroll
            for (int c = 0; c < CC; c++)
                Xs[c * 256 + tid] = __float2half_rn((vals[c] - mu) * rstd * __ldg(&ln_g[c]) + __ldg(&ln_b[c]));
        } else {
#pragma unroll
            for (int c = 0; c < CC; c++) Xs[c * 256 + tid] = __ushort_as_half((unsigned short)0);
        }
    }
    __syncthreads();

    // Phase 2: qproj
    {
        int p = tid >> 1;
        int posIdx = 64 + p;
        int o0 = (tid & 1) * 32;
        float acc[32] = {};
#pragma unroll 8
        for (int c = 0; c < CC; c++) {
            float xv = __half2float(Xs[c * 256 + posIdx]);
            const float4* wrow = (const float4*)&WqT[c * 64 + o0];
#pragma unroll
            for (int u = 0; u < 8; u++) {
                float4 w4 = wrow[u];
                acc[u * 4 + 0] += w4.x * xv;
                acc[u * 4 + 1] += w4.y * xv;
                acc[u * 4 + 2] += w4.z * xv;
                acc[u * 4 + 3] += w4.w * xv;
            }
        }
        int gpos = h0 * WW + p;
        __half* qdst = g_q + (size_t)(b * NNPOS + gpos) * CC + o0;
        uint32_t hx[16];
#pragma unroll
        for (int j = 0; j < 16; j++) {
            float a0 = (acc[2 * j]     + Bq[o0 + 2 * j])     * QSCALE;
            float a1 = (acc[2 * j + 1] + Bq[o0 + 2 * j + 1]) * QSCALE;
            hx[j] = h2u(__floats2half2_rn(a0, a1));
        }
#pragma unroll
        for (int j = 0; j < 4; j++)
            *(uint4*)(qdst + j * 8) = make_uint4(hx[4 * j], hx[4 * j + 1], hx[4 * j + 2], hx[4 * j + 3]);
    }

    // Phase 3: dwconv
#pragma unroll
    for (int r = 0; r < 2; r++) {
        int idx = tid + r * 256;
        int cg = idx >> 7;
        int p  = idx & 127;
        int hhp = 1 + (p >> 6);
        int wp = p & 63;
        int gpos = (h0 + (p >> 6)) * WW + wp;
        uint32_t khp[8];
        uint32_t khprev = 0;
#pragma unroll
        for (int ci = 0; ci < 16; ci++) {
            int c = cg * 16 + ci;
            const __half* xrow = Xs + c * 256;
            const float* wkp = Wk + c * 9;
            const float* wvp = Wv + c * 9;
            float sk = Bk[c], sv = Bv[c];
#pragma unroll
            for (int dh = 0; dh < 3; dh++) {
                int hs = (hhp + dh - 1) * 64;
#pragma unroll
                for (int dw = 0; dw < 3; dw++) {
                    int ws = wp + dw - 1;
                    if (ws < 0 || ws >= WW) continue;
                    float xv = __half2float(xrow[hs + ws]);
                    sk += xv * wkp[dh * 3 + dw];
                    sv += xv * wvp[dh * 3 + dw];
                }
            }
            g_v[(size_t)(b * CC + c) * NNPOS + gpos] = __float2half_rn(sv);
            uint32_t hb = (uint32_t)__half_as_ushort(__float2half_rn(sk));
            if (ci & 1) khp[ci >> 1] = khprev | (hb << 16);
            else khprev = hb;
        }
        __half* kdst = g_k + (size_t)(b * NNPOS + gpos) * CC + cg * 16;
        *(uint4*)kdst       = make_uint4(khp[0], khp[1], khp[2], khp[3]);
        *(uint4*)(kdst + 8) = make_uint4(khp[4], khp[5], khp[6], khp[7]);
    }
}

// ---------------------------------------------------------------------------
// 2) HMMA flash attention, split-KV (2 halves), partial O + l to scratch.
//    grid (32, B, 2) = 256 CTAs, 256 threads, 2 CTAs/SM target.
// ---------------------------------------------------------------------------
#define KROWB 144
#define VROWB 272
#define KBYTES (128 * KROWB)        // 18432
#define VBYTES (64 * VROWB)         // 17408
#define BUFB (KBYTES + VBYTES)      // 35840
#define ATTN_SMEM (2 * BUFB)        // 71680

__device__ __forceinline__ void prefetch_tile(char* smp, int s, int b, int jt, int tid) {
    {
        int j = tid >> 1, hf = tid & 1;
        const __half* src = g_k + (size_t)(b * NNPOS + jt + j) * CC + hf * 32;
        uint32_t dst = (uint32_t)__cvta_generic_to_shared(smp + s * BUFB + j * KROWB + hf * 64);
#pragma unroll
        for (int u = 0; u < 4; u++) cpasync16(dst + u * 16, src + u * 8);
    }
    {
        int c = tid >> 2, q = tid & 3;
        const __half* src = g_v + (size_t)(b * CC + c) * NNPOS + jt + q * 32;
        uint32_t dst = (uint32_t)__cvta_generic_to_shared(smp + s * BUFB + KBYTES + c * VROWB + q * 64);
#pragma unroll
        for (int u = 0; u < 4; u++) cpasync16(dst + u * 16, src + u * 8);
    }
}

__global__ __launch_bounds__(256, 2) void attn_kernel() {
    extern __shared__ char smp[];
    int tid = threadIdx.x;
    int w = tid >> 5, lane = tid & 31;
    int b = blockIdx.y;
    int i0 = blockIdx.x * 128;
    int half = blockIdx.z;
    int jt0 = half * 2048;
    int g = lane >> 2, t4 = lane & 3;

    int laneRowB = (lane & 7) + ((lane & 16) >> 1);
    int laneKB   = (lane & 8) << 1;
    uint32_t loffK = (uint32_t)(laneRowB * KROWB + laneKB);
    uint32_t loffV = (uint32_t)(laneRowB * VROWB + laneKB);
    uint32_t smbase = (uint32_t)__cvta_generic_to_shared(smp);

    prefetch_tile(smp, 0, b, jt0, tid);
    cpcommit();

    uint32_t qA[4][4];
    {
        size_t row0 = (size_t)(b * NNPOS + i0 + w * 16 + g) * CC;
        size_t row8 = row0 + 8 * CC;
#pragma unroll
        for (int ks = 0; ks < 4; ks++) {
            int col = 2 * t4 + 16 * ks;
            qA[ks][0] = *(const uint32_t*)(g_q + row0 + col);
            qA[ks][1] = *(const uint32_t*)(g_q + row8 + col);
            qA[ks][2] = *(const uint32_t*)(g_q + row0 + col + 8);
            qA[ks][3] = *(const uint32_t*)(g_q + row8 + col + 8);
        }
    }

    float oacc[8][4] = {};
    float lacc[4] = {};

    for (int tix = 0; tix < 16; tix++) {
        cpwait0();
        __syncthreads();
        if (tix < 15) { prefetch_tile(smp, (tix + 1) & 1, b, jt0 + (tix + 1) * 128, tid); cpcommit(); }

        uint32_t kb = smbase + (uint32_t)((tix & 1) * BUFB) + loffK;
        uint32_t vb = smbase + (uint32_t)((tix & 1) * BUFB + KBYTES) + loffV;

        // S = Q K^T (fp16 accumulate)
        uint32_t sacc16[16][2];
#pragma unroll
        for (int i = 0; i < 16; i++) { sacc16[i][0] = 0u; sacc16[i][1] = 0u; }
        {
            uint32_t b4[2][4];
            ldsm4(b4[0], kb);
#pragma unroll
            for (int it = 0; it < 32; it++) {
                int ks = it >> 3, np = it & 7;
                int cur = it & 1;
                if (it < 31) {
                    int nx = it + 1;
                    ldsm4(b4[cur ^ 1], kb + (uint32_t)((nx & 7) * (16 * KROWB) + (nx >> 3) * 32));
                }
                mma16816h(sacc16[2 * np],     qA[ks], b4[cur][0], b4[cur][1]);
                mma16816h(sacc16[2 * np + 1], qA[ks], b4[cur][2], b4[cur][3]);
            }
        }

        // p = 2^S; l via ones-MMA; O += P V^T
        {
            uint32_t v4[2][4];
            ldsm4(v4[0], vb);
#pragma unroll
            for (int ks2 = 0; ks2 < 8; ks2++) {
                uint32_t pA[4];
                pA[0] = ex2h2(sacc16[2 * ks2][0]);
                pA[1] = ex2h2(sacc16[2 * ks2][1]);
                pA[2] = ex2h2(sacc16[2 * ks2 + 1][0]);
                pA[3] = ex2h2(sacc16[2 * ks2 + 1][1]);
                mma16816(lacc, pA, ONES2, ONES2);
#pragma unroll
                for (int np = 0; np < 4; np++) {
                    int it = ks2 * 4 + np;
                    int cur = it & 1;
                    if (it < 31) {
                        int nx = it + 1;
                        ldsm4(v4[cur ^ 1], vb + (uint32_t)((nx & 3) * (16 * VROWB) + (nx >> 2) * 32));
                    }
                    mma16816(oacc[2 * np],     pA, v4[cur][0], v4[cur][1]);
                    mma16816(oacc[2 * np + 1], pA, v4[cur][2], v4[cur][3]);
                }
            }
        }
    }

    // write partial O (B,N,C fp32) + partial l
    int irow0 = i0 + w * 16 + g;
    float* po0 = g_po + (size_t)half * (BB * NNPOS * CC) + (size_t)(b * NNPOS + irow0) * CC;
    float* po8 = po0 + 8 * CC;
#pragma unroll
    for (int nt = 0; nt < 8; nt++) {
        int c = nt * 8 + 2 * t4;
        *(float2*)&po0[c] = make_float2(oacc[nt][0], oacc[nt][1]);
        *(float2*)&po8[c] = make_float2(oacc[nt][2], oacc[nt][3]);
    }
    if (t4 == 0) {
        g_pl[half * (BB * NNPOS) + b * NNPOS + irow0]     = lacc[0];
        g_pl[half * (BB * NNPOS) + b * NNPOS + irow0 + 8] = lacc[2];
    }
}

// ---------------------------------------------------------------------------
// 3) Combine: O = (O1+O2)/(l1+l2), out = O @ wo^T + bo + x. grid (32,B), 256thr.
// ---------------------------------------------------------------------------
#define WOROWB 144
#define COMB_SMEM (64 * WOROWB)     // 9216

__global__ __launch_bounds__(256) void combine_kernel(const float* __restrict__ wo,
                                                      const float* __restrict__ bo,
                                                      const float* __restrict__ x,
                                                      float* __restrict__ out) {
    extern __shared__ char csm[];
    int tid = threadIdx.x;
    int w = tid >> 5, lane = tid & 31;
    int b = blockIdx.y;
    int i0 = blockIdx.x * 128;
    int g = lane >> 2, t4 = lane & 3;

    int laneRowB = (lane & 7) + ((lane & 16) >> 1);
    int laneKB   = (lane & 8) << 1;
    uint32_t loffB = (uint32_t)(laneRowB * WOROWB + laneKB);
    uint32_t smbase = (uint32_t)__cvta_generic_to_shared(csm);

    // wo -> smem fp16 [o][c]
    {
        int o = tid >> 2, qq = tid & 3;
        const float* src = wo + o * 64 + qq * 16;
        uint32_t hx[8];
#pragma unroll
        for (int u = 0; u < 8; u++) {
            float2 f2 = *(const float2*)(src + u * 2);
            hx[u] = h2u(__floats2half2_rn(f2.x, f2.y));
        }
        char* dst = csm + o * WOROWB + qq * 32;
        *(uint4*)dst = make_uint4(hx[0], hx[1], hx[2], hx[3]);
        *(uint4*)(dst + 16) = make_uint4(hx[4], hx[5], hx[6], hx[7]);
    }
    __syncthreads();

    int irow0 = i0 + w * 16 + g;
    int lbase = b * NNPOS + irow0;
    float inv0 = 1.f / (__ldg(&g_pl[lbase]) + __ldg(&g_pl[BB * NNPOS + lbase]));
    float inv1 = 1.f / (__ldg(&g_pl[lbase + 8]) + __ldg(&g_pl[BB * NNPOS + lbase + 8]));

    const float* p10 = g_po + (size_t)(b * NNPOS + irow0) * CC;
    const float* p18 = p10 + 8 * CC;
    const float* p20 = p10 + (size_t)(BB * NNPOS * CC);
    const float* p28 = p20 + 8 * CC;

    uint32_t oA[4][4];
#pragma unroll
    for (int ks = 0; ks < 4; ks++) {
        int c0 = 16 * ks + 2 * t4;
        float2 aG  = *(const float2*)&p10[c0];
        float2 bG  = *(const float2*)&p20[c0];
        float2 aH  = *(const float2*)&p18[c0];
        float2 bH  = *(const float2*)&p28[c0];
        float2 aG2 = *(const float2*)&p10[c0 + 8];
        float2 bG2 = *(const float2*)&p20[c0 + 8];
        float2 aH2 = *(const float2*)&p18[c0 + 8];
        float2 bH2 = *(const float2*)&p28[c0 + 8];
        oA[ks][0] = h2u(__floats2half2_rn((aG.x + bG.x) * inv0,   (aG.y + bG.y) * inv0));
        oA[ks][1] = h2u(__floats2half2_rn((aH.x + bH.x) * inv1,   (aH.y + bH.y) * inv1));
        oA[ks][2] = h2u(__floats2half2_rn((aG2.x + bG2.x) * inv0, (aG2.y + bG2.y) * inv0));
        oA[ks][3] = h2u(__floats2half2_rn((aH2.x + bH2.x) * inv1, (aH2.y + bH2.y) * inv1));
    }

    float dacc[8][4] = {};
#pragma unroll
    for (int it = 0; it < 16; it++) {
        int ks = it >> 2, np = it & 3;
        uint32_t b4[4];
        ldsm4(b4, smbase + loffB + (uint32_t)(np * (16 * WOROWB) + ks * 32));
        mma16816(dacc[2 * np],     oA[ks], b4[0], b4[1]);
        mma16816(dacc[2 * np + 1], oA[ks], b4[2], b4[3]);
    }

#pragma unroll
    for (int nt = 0; nt < 8; nt++) {
        int o = nt * 8 + 2 * t4;
        float b0v = __ldg(&bo[o]), b1v = __ldg(&bo[o + 1]);
        size_t a00 = (size_t)(b * CC + o) * NNPOS + irow0;
        size_t a10 = a00 + NNPOS;
        out[a00]     = dacc[nt][0] + b0v + __ldg(&x[a00]);
        out[a10]     = dacc[nt][1] + b1v + __ldg(&x[a10]);
        out[a00 + 8] = dacc[nt][2] + b0v + __ldg(&x[a00 + 8]);
        out[a10 + 8] = dacc[nt][3] + b1v + __ldg(&x[a10 + 8]);
    }
}

// ---------------------------------------------------------------------------
extern "C" void kernel_launch(void* const* d_in, const int* in_sizes, int n_in,
                              void* d_out, int out_size) {
    (void)in_sizes; (void)n_in; (void)out_size;
    const float* x    = (const float*)d_in[0];
    const float* ln_g = (const float*)d_in[1];
    const float* ln_b = (const float*)d_in[2];
    const float* wq   = (const float*)d_in[3];
    const float* bq   = (const float*)d_in[4];
    const float* wk   = (const float*)d_in[5];
    const float* bk   = (const float*)d_in[6];
    const float* wv   = (const float*)d_in[7];
    const float* bv   = (const float*)d_in[8];
    const float* wo   = (const float*)d_in[9];
    const float* bo   = (const float*)d_in[10];
    float* out = (float*)d_out;

    cudaFuncSetAttribute(prep_kernel, cudaFuncAttributeMaxDynamicSharedMemorySize, PREP_SMEM);
    prep_kernel<<<dim3(32, BB), 256, PREP_SMEM>>>(x, ln_g, ln_b, wq, bq, wk, bk, wv, bv);
    cudaFuncSetAttribute(attn_kernel, cudaFuncAttributeMaxDynamicSharedMemorySize, ATTN_SMEM);
    attn_kernel<<<dim3(NNPOS / 128, BB, 2), 256, ATTN_SMEM>>>();
    combine_kernel<<<dim3(NNPOS / 128, BB), 256, COMB_SMEM>>>(wo, bo, x, out);
}

// round 12
// speedup vs baseline: 1.4425x; 1.0781x over previous
#include <cuda_runtime.h>
#include <cuda_fp16.h>
#include <cstdint>

#define BB 4
#define CC 64
#define NNPOS 4096
#define HH 64
#define WW 64

// Scratch (__device__ globals; no allocs allowed)
__device__ __half g_q[BB * NNPOS * CC];            // Q fp16 (B,N,C), x (0.125*log2e) folded
__device__ __half g_k[BB * CC * NNPOS];            // K fp16 (B,C,N)  <-- layout changed
__device__ __half g_v[BB * CC * NNPOS];            // V fp16 (B,C,N)
__device__ float  g_po[2 * BB * NNPOS * CC];       // partial O per key-half (B,N,C) fp32
__device__ float  g_pl[2 * BB * NNPOS];            // partial l per key-half

#define QSCALE 0.18033688011112293f   // 0.125 * log2(e)
#define ONES2 0x3C003C00u              // half2(1.0, 1.0)

// ---------------- helpers ----------------
__device__ __forceinline__ uint32_t h2u(__half2 h) { return *reinterpret_cast<uint32_t*>(&h); }
__device__ __forceinline__ uint32_t packh2(float a, float b) { return h2u(__floats2half2_rn(a, b)); }

__device__ __forceinline__ void ldsm4(uint32_t* r, uint32_t addr) {
    asm volatile("ldmatrix.sync.aligned.m8n8.x4.shared.b16 {%0,%1,%2,%3}, [%4];"
                 : "=r"(r[0]), "=r"(r[1]), "=r"(r[2]), "=r"(r[3]) : "r"(addr));
}
__device__ __forceinline__ void ldsm4t(uint32_t* r, uint32_t addr) {
    asm volatile("ldmatrix.sync.aligned.m8n8.x4.trans.shared.b16 {%0,%1,%2,%3}, [%4];"
                 : "=r"(r[0]), "=r"(r[1]), "=r"(r[2]), "=r"(r[3]) : "r"(addr));
}
__device__ __forceinline__ void mma16816(float* d, const uint32_t* a, uint32_t b0, uint32_t b1) {
    asm volatile("mma.sync.aligned.m16n8k16.row.col.f32.f16.f16.f32 "
                 "{%0,%1,%2,%3},{%4,%5,%6,%7},{%8,%9},{%0,%1,%2,%3};"
                 : "+f"(d[0]), "+f"(d[1]), "+f"(d[2]), "+f"(d[3])
                 : "r"(a[0]), "r"(a[1]), "r"(a[2]), "r"(a[3]), "r"(b0), "r"(b1));
}
__device__ __forceinline__ void mma16816h(uint32_t* d, const uint32_t* a, uint32_t b0, uint32_t b1) {
    asm volatile("mma.sync.aligned.m16n8k16.row.col.f16.f16.f16.f16 "
                 "{%0,%1},{%2,%3,%4,%5},{%6,%7},{%0,%1};"
                 : "+r"(d[0]), "+r"(d[1])
                 : "r"(a[0]), "r"(a[1]), "r"(a[2]), "r"(a[3]), "r"(b0), "r"(b1));
}
__device__ __forceinline__ void cpasync16(uint32_t dst, const void* src) {
    asm volatile("cp.async.cg.shared.global [%0], [%1], 16;" :: "r"(dst), "l"(src));
}
__device__ __forceinline__ void cpcommit() { asm volatile("cp.async.commit_group;"); }
__device__ __forceinline__ void cpwait0()  { asm volatile("cp.async.wait_group 0;"); }

__device__ __forceinline__ uint32_t ex2h2(uint32_t s) {
    uint32_t r;
    asm("ex2.approx.f16x2 %0, %1;" : "=r"(r) : "r"(s));
    return r;
}

// ---------------------------------------------------------------------------
// 1) Fused prep: LN + qproj + dwconv(k,v). grid (32, B), 256 threads.
//    Vectorized smem access; k and v both written (B,C,N) coalesced.
// ---------------------------------------------------------------------------
#define PR_XSTR  264                    // Xs row stride in halfs (conflict pad)
#define PR_WQT   0                      // fp32 [c][o]      16384
#define PR_WK    16384                  // fp32 [c*9]        2304
#define PR_WV    18688                  //                   2304
#define PR_BQ    20992                  // fp32 [64]          256
#define PR_BK    21248
#define PR_BV    21504
#define PR_XS    21760                  // fp16 [c][PR_XSTR]
#define PREP_SMEM (PR_XS + 64 * PR_XSTR * 2)   // 55552

__global__ __launch_bounds__(256) void prep_kernel(
    const float* __restrict__ x,
    const float* __restrict__ ln_g, const float* __restrict__ ln_b,
    const float* __restrict__ wq, const float* __restrict__ bq,
    const float* __restrict__ wk, const float* __restrict__ bk,
    const float* __restrict__ wv, const float* __restrict__ bv)
{
    extern __shared__ char psm[];
    float* WqT = (float*)(psm + PR_WQT);
    float* Wk  = (float*)(psm + PR_WK);
    float* Wv  = (float*)(psm + PR_WV);
    float* Bq  = (float*)(psm + PR_BQ);
    float* Bk  = (float*)(psm + PR_BK);
    float* Bv  = (float*)(psm + PR_BV);
    __half* Xs = (__half*)(psm + PR_XS);

    int tid = threadIdx.x;
    int h0 = blockIdx.x * 2;
    int b = blockIdx.y;

    for (int t = tid; t < 4096; t += 256) {
        int o = t >> 6, c = t & 63;
        WqT[c * 64 + o] = wq[t];
    }
    for (int t = tid; t < 576; t += 256) { Wk[t] = wk[t]; Wv[t] = wv[t]; }
    if (tid < 64) { Bq[tid] = bq[tid]; Bk[tid] = bk[tid]; Bv[tid] = bv[tid]; }

    // Phase 1: LN rows h0-1 .. h0+2 (zero pad) -> Xs[c][tid]
    {
        int hh = tid >> 6;
        int w  = tid & 63;
        int h = h0 - 1 + hh;
        if (h >= 0 && h < HH) {
            const float* xp = x + (size_t)b * CC * NNPOS + h * WW + w;
            float vals[CC];
            float s = 0.f;
#pragma unroll
            for (int c = 0; c < CC; c++) { vals[c] = xp[(size_t)c * NNPOS]; s += vals[c]; }
            float mu = s * (1.f / 64.f);
            float vs = 0.f;
#pragma unroll
            for (int c = 0; c < CC; c++) { float d = vals[c] - mu; vs += d * d; }
            float rstd = rsqrtf(vs * (1.f / 64.f) + 1e-5f);
#pragma unroll
            for (int c = 0; c < CC; c++)
                Xs[c * PR_XSTR + tid] = __float2half_rn((vals[c] - mu) * rstd * __ldg(&ln_g[c]) + __ldg(&ln_b[c]));
        } else {
#pragma unroll
            for (int c = 0; c < CC; c++) Xs[c * PR_XSTR + tid] = __ushort_as_half((unsigned short)0);
        }
    }
    __syncthreads();

    // Phase 2: qproj. thread = 4 positions (pg) x 8 outputs (og)
    {
        int pg = tid >> 3, og = tid & 7;
        float acc[4][8] = {};
#pragma unroll 4
        for (int c = 0; c < CC; c++) {
            uint2 raw = *(const uint2*)&Xs[c * PR_XSTR + 64 + pg * 4];
            float2 f01 = __half22float2(*(__half2*)&raw.x);
            float2 f23 = __half22float2(*(__half2*)&raw.y);
            float xv[4] = {f01.x, f01.y, f23.x, f23.y};
            const float4* wr = (const float4*)&WqT[c * 64 + og * 8];
            float4 wa = wr[0], wb = wr[1];
            float wv8[8] = {wa.x, wa.y, wa.z, wa.w, wb.x, wb.y, wb.z, wb.w};
#pragma unroll
            for (int s = 0; s < 4; s++)
#pragma unroll
                for (int o = 0; o < 8; o++)
                    acc[s][o] += xv[s] * wv8[o];
        }
        float bb8[8];
#pragma unroll
        for (int o = 0; o < 8; o++) bb8[o] = Bq[og * 8 + o];
#pragma unroll
        for (int s = 0; s < 4; s++) {
            int gpos = h0 * WW + pg * 4 + s;
            __half* qdst = g_q + (size_t)(b * NNPOS + gpos) * CC + og * 8;
            uint32_t hx[4];
#pragma unroll
            for (int j = 0; j < 4; j++)
                hx[j] = packh2((acc[s][2 * j] + bb8[2 * j]) * QSCALE,
                               (acc[s][2 * j + 1] + bb8[2 * j + 1]) * QSCALE);
            *(uint4*)qdst = make_uint4(hx[0], hx[1], hx[2], hx[3]);
        }
    }

    // Phase 3: dwconv. thread = (channel c, out-row, 32-wide strip)
    {
        int c = tid >> 2, row = (tid >> 1) & 1, wh = tid & 1;
        int wst = wh * 32;
        float wkr[9], wvr[9];
#pragma unroll
        for (int i = 0; i < 9; i++) { wkr[i] = Wk[c * 9 + i]; wvr[i] = Wv[c * 9 + i]; }
        float bk0 = Bk[c], bv0 = Bv[c];
        uint32_t kh[16], vh[16];
#pragma unroll
        for (int ch = 0; ch < 4; ch++) {
            int w0 = wst + ch * 8;
            float ff[3][10];
#pragma unroll
            for (int r = 0; r < 3; r++) {
                const __half* src = Xs + c * PR_XSTR + (row + r) * 64 + (w0 - 2);
                float2 t0 = __half22float2(*(const __half2*)(src));
                float2 t1 = __half22float2(*(const __half2*)(src + 2));
                float2 t2 = __half22float2(*(const __half2*)(src + 4));
                float2 t3 = __half22float2(*(const __half2*)(src + 6));
                float2 t4v = __half22float2(*(const __half2*)(src + 8));
                float2 t5 = __half22float2(*(const __half2*)(src + 10));
                ff[r][0] = t0.y; ff[r][1] = t1.x; ff[r][2] = t1.y; ff[r][3] = t2.x; ff[r][4] = t2.y;
                ff[r][5] = t3.x; ff[r][6] = t3.y; ff[r][7] = t4v.x; ff[r][8] = t4v.y; ff[r][9] = t5.x;
            }
            if (w0 == 0)  { ff[0][0] = 0.f; ff[1][0] = 0.f; ff[2][0] = 0.f; }
            if (w0 == 56) { ff[0][9] = 0.f; ff[1][9] = 0.f; ff[2][9] = 0.f; }
            float ko[8], vo[8];
#pragma unroll
            for (int o = 0; o < 8; o++) {
                float sk = bk0, sv = bv0;
#pragma unroll
                for (int r = 0; r < 3; r++)
#pragma unroll
                    for (int d = 0; d < 3; d++) {
                        float xv = ff[r][o + d];
                        sk += xv * wkr[r * 3 + d];
                        sv += xv * wvr[r * 3 + d];
                    }
                ko[o] = sk; vo[o] = sv;
            }
#pragma unroll
            for (int j = 0; j < 4; j++) {
                kh[ch * 4 + j] = packh2(ko[2 * j], ko[2 * j + 1]);
                vh[ch * 4 + j] = packh2(vo[2 * j], vo[2 * j + 1]);
            }
        }
        size_t base = (size_t)(b * CC + c) * NNPOS + (h0 + row) * WW + wst;
        __half* kd = g_k + base;
        __half* vd = g_v + base;
        *(uint4*)(kd)      = make_uint4(kh[0],  kh[1],  kh[2],  kh[3]);
        *(uint4*)(kd + 8)  = make_uint4(kh[4],  kh[5],  kh[6],  kh[7]);
        *(uint4*)(kd + 16) = make_uint4(kh[8],  kh[9],  kh[10], kh[11]);
        *(uint4*)(kd + 24) = make_uint4(kh[12], kh[13], kh[14], kh[15]);
        *(uint4*)(vd)      = make_uint4(vh[0],  vh[1],  vh[2],  vh[3]);
        *(uint4*)(vd + 8)  = make_uint4(vh[4],  vh[5],  vh[6],  vh[7]);
        *(uint4*)(vd + 16) = make_uint4(vh[8],  vh[9],  vh[10], vh[11]);
        *(uint4*)(vd + 24) = make_uint4(vh[12], vh[13], vh[14], vh[15]);
    }
}

// ---------------------------------------------------------------------------
// 2) HMMA flash attention, split-KV. K now (B,C,N) -> trans-ldmatrix.
//    grid (32, B, 2), 256 threads, 2 CTAs/SM.
// ---------------------------------------------------------------------------
#define TROWB 272
#define TBYTES (64 * TROWB)         // 17408
#define BUFB (2 * TBYTES)           // 34816
#define ATTN_SMEM (2 * BUFB)        // 69632

__device__ __forceinline__ void prefetch_tile(char* smp, int s, int b, int jt, int tid) {
    int c = tid >> 2, q = tid & 3;
    size_t src_off = (size_t)(b * CC + c) * NNPOS + jt + q * 32;
    uint32_t dst = (uint32_t)__cvta_generic_to_shared(smp + s * BUFB + c * TROWB + q * 64);
    const __half* ks = g_k + src_off;
    const __half* vs = g_v + src_off;
#pragma unroll
    for (int u = 0; u < 4; u++) cpasync16(dst + u * 16, ks + u * 8);
#pragma unroll
    for (int u = 0; u < 4; u++) cpasync16(dst + TBYTES + u * 16, vs + u * 8);
}

__global__ __launch_bounds__(256, 2) void attn_kernel() {
    extern __shared__ char smp[];
    int tid = threadIdx.x;
    int w = tid >> 5, lane = tid & 31;
    int b = blockIdx.y;
    int i0 = blockIdx.x * 128;
    int half = blockIdx.z;
    int jt0 = half * 2048;
    int g = lane >> 2, t4 = lane & 3;

    // K (trans) lane offset: rows = c (lane&15), j-half = (lane>>4)*8 cols
    uint32_t loffK = (uint32_t)((lane & 15) * TROWB + ((lane >> 4) << 4));
    // V (non-trans B) lane offset as before
    int laneRowB = (lane & 7) + ((lane & 16) >> 1);
    int laneKB   = (lane & 8) << 1;
    uint32_t loffV = (uint32_t)(laneRowB * TROWB + laneKB);
    uint32_t smbase = (uint32_t)__cvta_generic_to_shared(smp);

    prefetch_tile(smp, 0, b, jt0, tid);
    cpcommit();

    uint32_t qA[4][4];
    {
        size_t row0 = (size_t)(b * NNPOS + i0 + w * 16 + g) * CC;
        size_t row8 = row0 + 8 * CC;
#pragma unroll
        for (int ks = 0; ks < 4; ks++) {
            int col = 2 * t4 + 16 * ks;
            qA[ks][0] = *(const uint32_t*)(g_q + row0 + col);
            qA[ks][1] = *(const uint32_t*)(g_q + row8 + col);
            qA[ks][2] = *(const uint32_t*)(g_q + row0 + col + 8);
            qA[ks][3] = *(const uint32_t*)(g_q + row8 + col + 8);
        }
    }

    float oacc[8][4] = {};
    float lacc[4] = {};

    for (int tix = 0; tix < 16; tix++) {
        cpwait0();
        __syncthreads();
        if (tix < 15) { prefetch_tile(smp, (tix + 1) & 1, b, jt0 + (tix + 1) * 128, tid); cpcommit(); }

        uint32_t kb = smbase + (uint32_t)((tix & 1) * BUFB) + loffK;
        uint32_t vb = smbase + (uint32_t)((tix & 1) * BUFB + TBYTES) + loffV;

        // S = Q K^T (fp16 accumulate), K via trans-ldmatrix from [c][j] tile
        uint32_t sacc16[16][2];
#pragma unroll
        for (int i = 0; i < 16; i++) { sacc16[i][0] = 0u; sacc16[i][1] = 0u; }
        {
            uint32_t b4[2][4];
            ldsm4t(b4[0], kb);
#pragma unroll
            for (int it = 0; it < 32; it++) {
                int ks = it >> 3, np = it & 7;
                int cur = it & 1;
                if (it < 31) {
                    int nx = it + 1;
                    ldsm4t(b4[cur ^ 1], kb + (uint32_t)((nx & 7) * 32 + (nx >> 3) * (16 * TROWB)));
                }
                mma16816h(sacc16[2 * np],     qA[ks], b4[cur][0], b4[cur][1]);
                mma16816h(sacc16[2 * np + 1], qA[ks], b4[cur][2], b4[cur][3]);
            }
        }

        // p = 2^S; l via ones-MMA; O += P V^T
        {
            uint32_t v4[2][4];
            ldsm4(v4[0], vb);
#pragma unroll
            for (int ks2 = 0; ks2 < 8; ks2++) {
                uint32_t pA[4];
                pA[0] = ex2h2(sacc16[2 * ks2][0]);
                pA[1] = ex2h2(sacc16[2 * ks2][1]);
                pA[2] = ex2h2(sacc16[2 * ks2 + 1][0]);
                pA[3] = ex2h2(sacc16[2 * ks2 + 1][1]);
                mma16816(lacc, pA, ONES2, ONES2);
#pragma unroll
                for (int np = 0; np < 4; np++) {
                    int it = ks2 * 4 + np;
                    int cur = it & 1;
                    if (it < 31) {
                        int nx = it + 1;
                        ldsm4(v4[cur ^ 1], vb + (uint32_t)((nx & 3) * (16 * TROWB) + (nx >> 2) * 32));
                    }
                    mma16816(oacc[2 * np],     pA, v4[cur][0], v4[cur][1]);
                    mma16816(oacc[2 * np + 1], pA, v4[cur][2], v4[cur][3]);
                }
            }
        }
    }

    // write partial O (B,N,C fp32) + partial l
    int irow0 = i0 + w * 16 + g;
    float* po0 = g_po + (size_t)half * (BB * NNPOS * CC) + (size_t)(b * NNPOS + irow0) * CC;
    float* po8 = po0 + 8 * CC;
#pragma unroll
    for (int nt = 0; nt < 8; nt++) {
        int c = nt * 8 + 2 * t4;
        *(float2*)&po0[c] = make_float2(oacc[nt][0], oacc[nt][1]);
        *(float2*)&po8[c] = make_float2(oacc[nt][2], oacc[nt][3]);
    }
    if (t4 == 0) {
        g_pl[half * (BB * NNPOS) + b * NNPOS + irow0]     = lacc[0];
        g_pl[half * (BB * NNPOS) + b * NNPOS + irow0 + 8] = lacc[2];
    }
}

// ---------------------------------------------------------------------------
// 3) Combine: O = (O1+O2)/(l1+l2), out = O @ wo^T + bo + x.
// ---------------------------------------------------------------------------
#define WOROWB 144
#define COMB_SMEM (64 * WOROWB)

__global__ __launch_bounds__(256) void combine_kernel(const float* __restrict__ wo,
                                                      const float* __restrict__ bo,
                                                      const float* __restrict__ x,
                                                      float* __restrict__ out) {
    extern __shared__ char csm[];
    int tid = threadIdx.x;
    int w = tid >> 5, lane = tid & 31;
    int b = blockIdx.y;
    int i0 = blockIdx.x * 128;
    int g = lane >> 2, t4 = lane & 3;

    int laneRowB = (lane & 7) + ((lane & 16) >> 1);
    int laneKB   = (lane & 8) << 1;
    uint32_t loffB = (uint32_t)(laneRowB * WOROWB + laneKB);
    uint32_t smbase = (uint32_t)__cvta_generic_to_shared(csm);

    {
        int o = tid >> 2, qq = tid & 3;
        const float* src = wo + o * 64 + qq * 16;
        uint32_t hx[8];
#pragma unroll
        for (int u = 0; u < 8; u++) {
            float2 f2 = *(const float2*)(src + u * 2);
            hx[u] = packh2(f2.x, f2.y);
        }
        char* dst = csm + o * WOROWB + qq * 32;
        *(uint4*)dst = make_uint4(hx[0], hx[1], hx[2], hx[3]);
        *(uint4*)(dst + 16) = make_uint4(hx[4], hx[5], hx[6], hx[7]);
    }
    __syncthreads();

    int irow0 = i0 + w * 16 + g;
    int lbase = b * NNPOS + irow0;
    float inv0 = 1.f / (__ldg(&g_pl[lbase]) + __ldg(&g_pl[BB * NNPOS + lbase]));
    float inv1 = 1.f / (__ldg(&g_pl[lbase + 8]) + __ldg(&g_pl[BB * NNPOS + lbase + 8]));

    const float* p10 = g_po + (size_t)(b * NNPOS + irow0) * CC;
    const float* p18 = p10 + 8 * CC;
    const float* p20 = p10 + (size_t)(BB * NNPOS * CC);
    const float* p28 = p20 + 8 * CC;

    uint32_t oA[4][4];
#pragma unroll
    for (int ks = 0; ks < 4; ks++) {
        int c0 = 16 * ks + 2 * t4;
        float2 aG  = *(const float2*)&p10[c0];
        float2 bG  = *(const float2*)&p20[c0];
        float2 aH  = *(const float2*)&p18[c0];
        float2 bH  = *(const float2*)&p28[c0];
        float2 aG2 = *(const float2*)&p10[c0 + 8];
        float2 bG2 = *(const float2*)&p20[c0 + 8];
        float2 aH2 = *(const float2*)&p18[c0 + 8];
        float2 bH2 = *(const float2*)&p28[c0 + 8];
        oA[ks][0] = packh2((aG.x + bG.x) * inv0,   (aG.y + bG.y) * inv0);
        oA[ks][1] = packh2((aH.x + bH.x) * inv1,   (aH.y + bH.y) * inv1);
        oA[ks][2] = packh2((aG2.x + bG2.x) * inv0, (aG2.y + bG2.y) * inv0);
        oA[ks][3] = packh2((aH2.x + bH2.x) * inv1, (aH2.y + bH2.y) * inv1);
    }

    float dacc[8][4] = {};
#pragma unroll
    for (int it = 0; it < 16; it++) {
        int ks = it >> 2, np = it & 3;
        uint32_t b4[4];
        ldsm4(b4, smbase + loffB + (uint32_t)(np * (16 * WOROWB) + ks * 32));
        mma16816(dacc[2 * np],     oA[ks], b4[0], b4[1]);
        mma16816(dacc[2 * np + 1], oA[ks], b4[2], b4[3]);
    }

#pragma unroll
    for (int nt = 0; nt < 8; nt++) {
        int o = nt * 8 + 2 * t4;
        float b0v = __ldg(&bo[o]), b1v = __ldg(&bo[o + 1]);
        size_t a00 = (size_t)(b * CC + o) * NNPOS + irow0;
        size_t a10 = a00 + NNPOS;
        out[a00]     = dacc[nt][0] + b0v + __ldg(&x[a00]);
        out[a10]     = dacc[nt][1] + b1v + __ldg(&x[a10]);
        out[a00 + 8] = dacc[nt][2] + b0v + __ldg(&x[a00 + 8]);
        out[a10 + 8] = dacc[nt][3] + b1v + __ldg(&x[a10 + 8]);
    }
}

// ---------------------------------------------------------------------------
extern "C" void kernel_launch(void* const* d_in, const int* in_sizes, int n_in,
                              void* d_out, int out_size) {
    (void)in_sizes; (void)n_in; (void)out_size;
    const float* x    = (const float*)d_in[0];
    const float* ln_g = (const float*)d_in[1];
    const float* ln_b = (const float*)d_in[2];
    const float* wq   = (const float*)d_in[3];
    const float* bq   = (const float*)d_in[4];
    const float* wk   = (const float*)d_in[5];
    const float* bk   = (const float*)d_in[6];
    const float* wv   = (const float*)d_in[7];
    const float* bv   = (const float*)d_in[8];
    const float* wo   = (const float*)d_in[9];
    const float* bo   = (const float*)d_in[10];
    float* out = (float*)d_out;

    cudaFuncSetAttribute(prep_kernel, cudaFuncAttributeMaxDynamicSharedMemorySize, PREP_SMEM);
    prep_kernel<<<dim3(32, BB), 256, PREP_SMEM>>>(x, ln_g, ln_b, wq, bq, wk, bk, wv, bv);
    cudaFuncSetAttribute(attn_kernel, cudaFuncAttributeMaxDynamicSharedMemorySize, ATTN_SMEM);
    attn_kernel<<<dim3(NNPOS / 128, BB, 2), 256, ATTN_SMEM>>>();
    combine_kernel<<<dim3(NNPOS / 128, BB), 256, COMB_SMEM>>>(wo, bo, x, out);
}